// round 11
// baseline (speedup 1.0000x reference)
#include <cuda_runtime.h>
#include <cuda_bf16.h>
#include <math.h>
#include <stdint.h>

#define Nn 50000
#define Ee 400000
#define Gg 8
#define H  128
#define REPEATS 3
#define LDA 136

// ---------------- scratch (device globals; no allocation allowed) ----------
__device__ float g_h[Nn * H];
__device__ float g_t[Nn * H];
__device__ float g_P[Nn * H];
__device__ float g_Q[Nn * H];
__device__ float g_R[Nn * H];
__device__ float g_agg[Nn * H];
__device__ float g_cnt[Nn];
__device__ float g_gsum3[REPEATS][Gg * H];   // per-repeat sum buffers
__device__ float g_bcsum[Gg * H];
__device__ float g_xbc[Gg * H];
__device__ float g_gvec[Gg * H];
__device__ float g_gc[Gg];
__device__ float g_bccnt[Gg];
// pre-split bf16 weight images: 8 units x (32KB hi + 32KB lo), [n][k] layout
__device__ __align__(128) unsigned char g_wimg[8][65536];

// ---------------- mma/ldmatrix helpers (baseline PTX, sm_80+) ---------------
__device__ __forceinline__ uint32_t smem_u32(const void* p) {
    return (uint32_t)__cvta_generic_to_shared(p);
}
__device__ __forceinline__ void ldsm4(uint32_t* r, uint32_t addr) {
    asm volatile(
        "ldmatrix.sync.aligned.m8n8.x4.shared.b16 {%0,%1,%2,%3}, [%4];"
        : "=r"(r[0]), "=r"(r[1]), "=r"(r[2]), "=r"(r[3]) : "r"(addr));
}
__device__ __forceinline__ void mma16816(float* c, const uint32_t* a,
                                         uint32_t b0, uint32_t b1) {
    asm volatile(
        "mma.sync.aligned.m16n8k16.row.col.f32.bf16.bf16.f32 "
        "{%0,%1,%2,%3}, {%4,%5,%6,%7}, {%8,%9}, {%0,%1,%2,%3};"
        : "+f"(c[0]), "+f"(c[1]), "+f"(c[2]), "+f"(c[3])
        : "r"(a[0]), "r"(a[1]), "r"(a[2]), "r"(a[3]), "r"(b0), "r"(b1));
}

// ---------------- shared staging + compute helpers ---------------------------
__device__ __forceinline__ void stage_B(const unsigned char* __restrict__ wimg,
                                        __nv_bfloat16* Bh, __nv_bfloat16* Bl,
                                        int tid) {
    const uint4* bsrc = (const uint4*)wimg;
#pragma unroll
    for (int i = 0; i < 8; i++) {
        int idx = i * 512 + tid;        // 4096 uint4 (hi then lo)
        uint4 v = bsrc[idx];
        int half = idx >> 11;
        int e = idx & 2047;
        int n = e >> 4, kc = (e & 15) * 8;
        __nv_bfloat16* dst = half ? Bl : Bh;
        *(uint4*)&dst[n * LDA + kc] = v;
    }
}

// PART=0: store hi split of A; PART=1: store lo split (re-reads A from L2)
template <int PART>
__device__ __forceinline__ void stage_A_part(const float* __restrict__ A,
                                             int rowBase, int M,
                                             __nv_bfloat16* Adst, int tid) {
#pragma unroll
    for (int i = 0; i < 8; i++) {
        int fidx = i * 512 + tid;       // 4096 float4
        int r = fidx >> 5, c4 = (fidx & 31) * 4;
        float4 v = make_float4(0.f, 0.f, 0.f, 0.f);
        if (rowBase + r < M) v = *(const float4*)&A[(rowBase + r) * H + c4];
        unsigned short h0 = __bfloat16_as_ushort(__float2bfloat16(v.x));
        unsigned short h1 = __bfloat16_as_ushort(__float2bfloat16(v.y));
        unsigned short h2 = __bfloat16_as_ushort(__float2bfloat16(v.z));
        unsigned short h3 = __bfloat16_as_ushort(__float2bfloat16(v.w));
        uint2 pk;
        if (PART == 0) {
            pk = make_uint2((uint32_t)h0 | ((uint32_t)h1 << 16),
                            (uint32_t)h2 | ((uint32_t)h3 << 16));
        } else {
            float r0 = v.x - __bfloat162float(__ushort_as_bfloat16(h0));
            float r1 = v.y - __bfloat162float(__ushort_as_bfloat16(h1));
            float r2 = v.z - __bfloat162float(__ushort_as_bfloat16(h2));
            float r3 = v.w - __bfloat162float(__ushort_as_bfloat16(h3));
            unsigned short l0 = __bfloat16_as_ushort(__float2bfloat16(r0));
            unsigned short l1 = __bfloat16_as_ushort(__float2bfloat16(r1));
            unsigned short l2 = __bfloat16_as_ushort(__float2bfloat16(r2));
            unsigned short l3 = __bfloat16_as_ushort(__float2bfloat16(r3));
            pk = make_uint2((uint32_t)l0 | ((uint32_t)l1 << 16),
                            (uint32_t)l2 | ((uint32_t)l3 << 16));
        }
        *(uint2*)&Adst[r * LDA + c4] = pk;
    }
}

// one pass over K=128: acc += Ab @ Bb^T
__device__ __forceinline__ void mma_pass(const __nv_bfloat16* Ab,
                                         const __nv_bfloat16* Bb, int aoff,
                                         int boff, float acc[2][4][4]) {
#pragma unroll
    for (int kk = 0; kk < 8; kk++) {
        int k0 = kk * 16;
        uint32_t a[2][4], b[2][4];
#pragma unroll
        for (int mt = 0; mt < 2; mt++)
            ldsm4(a[mt], smem_u32(&Ab[aoff + mt * 16 * LDA + k0]));
#pragma unroll
        for (int np = 0; np < 2; np++)
            ldsm4(b[np], smem_u32(&Bb[boff + np * 16 * LDA + k0]));
#pragma unroll
        for (int mt = 0; mt < 2; mt++)
#pragma unroll
            for (int nt = 0; nt < 4; nt++)
                mma16816(acc[mt][nt], a[mt], b[nt >> 1][(nt & 1) * 2],
                         b[nt >> 1][(nt & 1) * 2 + 1]);
    }
}

// ---------------- weight prep: split f32 W[k][n] -> bf16 hi/lo [n][k] -------
__global__ void wprep_kernel(const float* __restrict__ We2,
                             const float* __restrict__ Wm1,
                             const float* __restrict__ Wm2,
                             const float* __restrict__ Wu1,
                             const float* __restrict__ Wu2,
                             const float* __restrict__ Wd1) {
    int unit = blockIdx.x >> 6;
    int t = (blockIdx.x & 63) * 256 + threadIdx.x;
    int n = t & 127, k = t >> 7;
    const float* src;
    switch (unit) {
        case 0: src = We2; break;
        case 1: src = Wm1; break;
        case 2: src = Wm1 + 128 * H; break;
        case 3: src = Wm2; break;
        case 4: src = Wu1; break;
        case 5: src = Wu1 + 128 * H; break;
        case 6: src = Wu2; break;
        default: src = Wd1; break;
    }
    float v = src[k * H + n];
    __nv_bfloat16 hb = __float2bfloat16(v);
    __nv_bfloat16 lb = __float2bfloat16(v - __bfloat162float(hb));
    unsigned short* img = (unsigned short*)(g_wimg[unit]);
    img[n * 128 + k] = __bfloat16_as_ushort(hb);
    img[16384 + n * 128 + k] = __bfloat16_as_ushort(lb);
}

// ---------------- node GEMM, 128-row tiles, A-buffer reuse -> 2 CTAs/SM -----
#define SMEM_G (3 * 128 * LDA * 2)
template <bool RELU, bool RESID>
__global__ __launch_bounds__(512, 2) void gemm_tc(
    const float* __restrict__ A, const unsigned char* __restrict__ wimg,
    const float* __restrict__ colbias, const float* __restrict__ rowdiv,
    float* __restrict__ C, const float* __restrict__ selfP,
    float* __restrict__ selfR, int M) {
    extern __shared__ __align__(16) unsigned char smem[];
    __nv_bfloat16* Ah = (__nv_bfloat16*)smem;        // reused for hi then lo
    __nv_bfloat16* Bh = Ah + 128 * LDA;
    __nv_bfloat16* Bl = Bh + 128 * LDA;
    int tid = threadIdx.x, lane = tid & 31, wid = tid >> 5;
    int rowBase = blockIdx.x * 128;

    stage_B(wimg, Bh, Bl, tid);
    stage_A_part<0>(A, rowBase, M, Ah, tid);
    __syncthreads();

    int warp_m = (wid & 3) * 32, warp_n = (wid >> 2) * 32;
    float acc[2][4][4];
#pragma unroll
    for (int mt = 0; mt < 2; mt++)
#pragma unroll
        for (int nt = 0; nt < 4; nt++)
#pragma unroll
            for (int q = 0; q < 4; q++) acc[mt][nt][q] = 0.f;

    int tq = lane >> 3, tr = lane & 7;
    int aoff = (warp_m + (tq & 1) * 8 + tr) * LDA + (tq >> 1) * 8;
    int boff = (warp_n + (tq >> 1) * 8 + tr) * LDA + (tq & 1) * 8;

    mma_pass(Ah, Bh, aoff, boff, acc);   // Ah*Bh
    mma_pass(Ah, Bl, aoff, boff, acc);   // Ah*Bl
    __syncthreads();
    stage_A_part<1>(A, rowBase, M, Ah, tid);   // overwrite with lo split
    __syncthreads();
    mma_pass(Ah, Bh, aoff, boff, acc);   // Al*Bh

#pragma unroll
    for (int mt = 0; mt < 2; mt++) {
#pragma unroll
        for (int half = 0; half < 2; half++) {
            int grow = rowBase + warp_m + mt * 16 + (lane >> 2) + half * 8;
            if (grow >= M) continue;
            float inv = 1.f;
            if (rowdiv) inv = 1.f / rowdiv[grow];
#pragma unroll
            for (int nt = 0; nt < 4; nt++) {
                int col = warp_n + nt * 8 + (lane & 3) * 2;
                float v0 = acc[mt][nt][half * 2 + 0];
                float v1 = acc[mt][nt][half * 2 + 1];
                if (rowdiv) { v0 *= inv; v1 *= inv; }
                if (colbias) { v0 += colbias[col]; v1 += colbias[col + 1]; }
                float* cp = &C[grow * H + col];
                if (RESID) {
                    float2 o = *(const float2*)cp;
                    v0 += o.x; v1 += o.y;
                }
                if (RELU) { v0 = fmaxf(v0, 0.f); v1 = fmaxf(v1, 0.f); }
                *(float2*)cp = make_float2(v0, v1);
                if (selfR) {
                    const float2 pp = *(const float2*)&selfP[grow * H + col];
                    *(float2*)&selfR[grow * H + col] =
                        make_float2(fmaxf(pp.x + v0, 0.f),
                                    fmaxf(pp.y + v1, 0.f));
                }
            }
        }
    }
}

// ---------------- fused update GEMM: t = relu(h@W4 + agg@W5 + gvec[batch]) --
__global__ __launch_bounds__(512, 2) void gemm_u1(
    const float* __restrict__ A1, const float* __restrict__ A2,
    const unsigned char* __restrict__ w4, const unsigned char* __restrict__ w5,
    const float* __restrict__ gvec, const int* __restrict__ batch,
    float* __restrict__ T, int M) {
    extern __shared__ __align__(16) unsigned char smem[];
    __nv_bfloat16* Ah = (__nv_bfloat16*)smem;
    __nv_bfloat16* Bh = Ah + 128 * LDA;
    __nv_bfloat16* Bl = Bh + 128 * LDA;
    int tid = threadIdx.x, lane = tid & 31, wid = tid >> 5;
    int rowBase = blockIdx.x * 128;

    int warp_m = (wid & 3) * 32, warp_n = (wid >> 2) * 32;
    float acc[2][4][4];
#pragma unroll
    for (int mt = 0; mt < 2; mt++)
#pragma unroll
        for (int nt = 0; nt < 4; nt++)
#pragma unroll
            for (int q = 0; q < 4; q++) acc[mt][nt][q] = 0.f;

    int tq = lane >> 3, tr = lane & 7;
    int aoff = (warp_m + (tq & 1) * 8 + tr) * LDA + (tq >> 1) * 8;
    int boff = (warp_n + (tq >> 1) * 8 + tr) * LDA + (tq & 1) * 8;

#pragma unroll
    for (int ph = 0; ph < 2; ph++) {
        const float* Ap = ph ? A2 : A1;
        const unsigned char* wp = ph ? w5 : w4;
        stage_B(wp, Bh, Bl, tid);
        stage_A_part<0>(Ap, rowBase, M, Ah, tid);
        __syncthreads();
        mma_pass(Ah, Bh, aoff, boff, acc);
        mma_pass(Ah, Bl, aoff, boff, acc);
        __syncthreads();
        stage_A_part<1>(Ap, rowBase, M, Ah, tid);
        __syncthreads();
        mma_pass(Ah, Bh, aoff, boff, acc);
        __syncthreads();
    }

#pragma unroll
    for (int mt = 0; mt < 2; mt++) {
#pragma unroll
        for (int half = 0; half < 2; half++) {
            int grow = rowBase + warp_m + mt * 16 + (lane >> 2) + half * 8;
            if (grow >= M) continue;
            const float* gv = &gvec[batch[grow] * H];
#pragma unroll
            for (int nt = 0; nt < 4; nt++) {
                int col = warp_n + nt * 8 + (lane & 3) * 2;
                float v0 = acc[mt][nt][half * 2 + 0] + gv[col];
                float v1 = acc[mt][nt][half * 2 + 1] + gv[col + 1];
                *(float2*)&T[grow * H + col] =
                    make_float2(fmaxf(v0, 0.f), fmaxf(v1, 0.f));
            }
        }
    }
}

// ---------------- small utility kernels ------------------------------------
__global__ void zero_all_kernel() {
    int i = blockIdx.x * 256 + threadIdx.x;   // grid 16 x 256 = 4096
    if (i < REPEATS * Gg * H) ((float*)g_gsum3)[i] = 0.f;
    if (i < Gg * H) g_bcsum[i] = 0.f;
    if (i < Gg) { g_gc[i] = 0.f; g_bccnt[i] = 0.f; }
}

__global__ void node_stats_kernel(const int* __restrict__ batch,
                                  const float* __restrict__ x_mask) {
    __shared__ float sgc[Gg], sbc[Gg];
    int tid = threadIdx.x;
    if (tid < Gg) { sgc[tid] = 0.f; sbc[tid] = 0.f; }
    __syncthreads();
    int n = blockIdx.x * 256 + tid;
    if (n < Nn) {
        int g = batch[n];
        float bc = x_mask[n * 3 + 2];
        atomicAdd(&sgc[g], 1.f);
        atomicAdd(&sbc[g], bc);
        g_cnt[n] = 1.f;
    }
    __syncthreads();
    if (tid < Gg) {
        atomicAdd(&g_gc[tid], sgc[tid]);
        atomicAdd(&g_bccnt[tid], sbc[tid]);
    }
}

__global__ void edge_cnt_kernel(const int* __restrict__ ei) {
    int e = blockIdx.x * 256 + threadIdx.x;
    if (e < Ee) atomicAdd(&g_cnt[ei[Ee + e]], 1.f);
}

__global__ void enc1_kernel(const float* __restrict__ x,
                            const float* __restrict__ xm,
                            const float* __restrict__ W_e1,
                            const float* __restrict__ b_e1) {
    __shared__ float Ws[8 * H];
    __shared__ float bs[H];
    int tid = threadIdx.x;
    for (int i = tid; i < 8 * H; i += 256) Ws[i] = W_e1[i];
    if (tid < H) bs[tid] = b_e1[tid];
    __syncthreads();
    int idx = blockIdx.x * 256 + tid;
    if (idx >= Nn * 32) return;
    int n = idx >> 5, j4 = (idx & 31) * 4;
    float in8[8];
#pragma unroll
    for (int k = 0; k < 5; k++) in8[k] = x[n * 5 + k];
#pragma unroll
    for (int k = 0; k < 3; k++) in8[5 + k] = xm[n * 3 + k];
    float4 acc = *(const float4*)&bs[j4];
#pragma unroll
    for (int k = 0; k < 8; k++) {
        float4 w = *(const float4*)&Ws[k * H + j4];
        acc.x = fmaf(in8[k], w.x, acc.x);
        acc.y = fmaf(in8[k], w.y, acc.y);
        acc.z = fmaf(in8[k], w.z, acc.z);
        acc.w = fmaf(in8[k], w.w, acc.w);
    }
    acc.x = fmaxf(acc.x, 0.f); acc.y = fmaxf(acc.y, 0.f);
    acc.z = fmaxf(acc.z, 0.f); acc.w = fmaxf(acc.w, 0.f);
    *(float4*)&g_t[n * H + j4] = acc;
}

__global__ __launch_bounds__(256) void edge_msg_kernel(
    const int* __restrict__ ei, const float* __restrict__ ea,
    const float* __restrict__ W_m1) {
    __shared__ float Wea[3 * H];
    int tid = threadIdx.x;
    for (int i = tid; i < 3 * H; i += 256) Wea[i] = W_m1[256 * H + i];
    __syncthreads();
    int e = blockIdx.x * 8 + (tid >> 5);
    if (e >= Ee) return;
    int lane = tid & 31;
    int src = ei[e];
    int dst = ei[Ee + e];
    float e0 = __ldg(&ea[e * 3 + 0]);
    float e1 = __ldg(&ea[e * 3 + 1]);
    float e2 = __ldg(&ea[e * 3 + 2]);
    int c = lane * 4;
    float4 p = *(const float4*)&g_P[src * H + c];
    float4 q = *(const float4*)&g_Q[dst * H + c];
    float4 w0 = *(const float4*)&Wea[0 * H + c];
    float4 w1 = *(const float4*)&Wea[1 * H + c];
    float4 w2 = *(const float4*)&Wea[2 * H + c];
    float vx = fmaxf(p.x + q.x + e0 * w0.x + e1 * w1.x + e2 * w2.x, 0.f);
    float vy = fmaxf(p.y + q.y + e0 * w0.y + e1 * w1.y + e2 * w2.y, 0.f);
    float vz = fmaxf(p.z + q.z + e0 * w0.z + e1 * w1.z + e2 * w2.z, 0.f);
    float vw = fmaxf(p.w + q.w + e0 * w0.w + e1 * w1.w + e2 * w2.w, 0.f);
    float* rp = &g_R[dst * H + c];
    asm volatile("red.global.add.v4.f32 [%0], {%1, %2, %3, %4};"
                 :: "l"(rp), "f"(vx), "f"(vy), "f"(vz), "f"(vw)
                 : "memory");
}

__global__ void group_sum_kernel(const int* __restrict__ batch,
                                 const float* __restrict__ x_mask,
                                 float* __restrict__ gsum, int withbc) {
    int j = threadIdx.x;
    int chunk = (Nn + gridDim.x - 1) / gridDim.x;
    int n0 = blockIdx.x * chunk;
    int n1 = n0 + chunk;
    if (n1 > Nn) n1 = Nn;
    if (n0 >= n1) return;
    float acc = 0.f, accb = 0.f;
    int gcur = batch[n0];
    for (int n = n0; n < n1; n++) {
        int g = batch[n];
        if (g != gcur) {
            atomicAdd(&gsum[gcur * H + j], acc);
            if (withbc) atomicAdd(&g_bcsum[gcur * H + j], accb);
            acc = 0.f; accb = 0.f; gcur = g;
        }
        float v = g_h[n * H + j];
        acc += v;
        if (withbc) accb += v * x_mask[n * 3 + 2];
    }
    atomicAdd(&gsum[gcur * H + j], acc);
    if (withbc) atomicAdd(&g_bcsum[gcur * H + j], accb);
}

__global__ void finalize_bc_kernel() {
    int g = blockIdx.x, j = threadIdx.x;
    float cb = fmaxf(g_bccnt[g], 1.f);
    g_xbc[g * H + j] = g_bcsum[g * H + j] / cb;
}

// gvec[g] = b_u1 + (gsum[g]/cnt) @ W_u1[256:384] + xbc[g] @ W_u1[384:512]
__global__ void fm_gvec_kernel(const float* __restrict__ gsum,
                               const float* __restrict__ W_u1,
                               const float* __restrict__ b_u1) {
    __shared__ float xg[H], xb[H];
    int g = blockIdx.x, j = threadIdx.x;
    float c = fmaxf(g_gc[g], 1.f);
    xg[j] = gsum[g * H + j] / c;
    xb[j] = g_xbc[g * H + j];
    __syncthreads();
    float acc = b_u1[j];
    for (int k = 0; k < H; k++) {
        acc = fmaf(xg[k], W_u1[(256 + k) * H + j], acc);
        acc = fmaf(xb[k], W_u1[(384 + k) * H + j], acc);
    }
    g_gvec[g * H + j] = acc;
}

__global__ void dec2_kernel(const float* __restrict__ W_d2,
                            const float* __restrict__ b_d2,
                            float* __restrict__ out) {
    int n = blockIdx.x * 8 + (threadIdx.x >> 5);
    if (n >= Nn) return;
    int lane = threadIdx.x & 31;
    float4 t4 = *(const float4*)&g_t[n * H + lane * 4];
    float tv[4] = {t4.x, t4.y, t4.z, t4.w};
    float a0 = 0.f, a1 = 0.f, a2 = 0.f;
#pragma unroll
    for (int r = 0; r < 4; r++) {
        int k = lane * 4 + r;
        a0 = fmaf(tv[r], __ldg(&W_d2[k * 3 + 0]), a0);
        a1 = fmaf(tv[r], __ldg(&W_d2[k * 3 + 1]), a1);
        a2 = fmaf(tv[r], __ldg(&W_d2[k * 3 + 2]), a2);
    }
#pragma unroll
    for (int off = 16; off; off >>= 1) {
        a0 += __shfl_down_sync(0xffffffffu, a0, off);
        a1 += __shfl_down_sync(0xffffffffu, a1, off);
        a2 += __shfl_down_sync(0xffffffffu, a2, off);
    }
    if (lane == 0) {
        out[n * 3 + 0] = a0 + b_d2[0];
        out[n * 3 + 1] = a1 + b_d2[1];
        out[n * 3 + 2] = a2 + b_d2[2];
    }
}

// ---------------- launch -----------------------------------------------------
extern "C" void kernel_launch(void* const* d_in, const int* in_sizes, int n_in,
                              void* d_out, int out_size) {
    const float* x    = (const float*)d_in[0];
    const float* xm   = (const float*)d_in[1];
    const float* ea   = (const float*)d_in[2];
    const float* W_e1 = (const float*)d_in[4];
    const float* b_e1 = (const float*)d_in[5];
    const float* W_e2 = (const float*)d_in[6];
    const float* b_e2 = (const float*)d_in[7];
    const float* W_m1 = (const float*)d_in[8];
    const float* b_m1 = (const float*)d_in[9];
    const float* W_m2 = (const float*)d_in[10];
    const float* b_m2 = (const float*)d_in[11];
    const float* W_u1 = (const float*)d_in[12];
    const float* b_u1 = (const float*)d_in[13];
    const float* W_u2 = (const float*)d_in[14];
    const float* b_u2 = (const float*)d_in[15];
    const float* W_d1 = (const float*)d_in[16];
    const float* b_d1 = (const float*)d_in[17];
    const float* W_d2 = (const float*)d_in[18];
    const float* b_d2 = (const float*)d_in[19];
    const int*   ei   = (const int*)d_in[20];
    const int*   batch = (const int*)d_in[21];
    float* out = (float*)d_out;

    float *p_h, *p_t, *p_P, *p_Q, *p_R, *p_agg, *p_cnt, *p_gvec, *p_gs;
    unsigned char* p_w;
    cudaGetSymbolAddress((void**)&p_h, g_h);
    cudaGetSymbolAddress((void**)&p_t, g_t);
    cudaGetSymbolAddress((void**)&p_P, g_P);
    cudaGetSymbolAddress((void**)&p_Q, g_Q);
    cudaGetSymbolAddress((void**)&p_R, g_R);
    cudaGetSymbolAddress((void**)&p_agg, g_agg);
    cudaGetSymbolAddress((void**)&p_cnt, g_cnt);
    cudaGetSymbolAddress((void**)&p_gvec, g_gvec);
    cudaGetSymbolAddress((void**)&p_gs, g_gsum3);
    cudaGetSymbolAddress((void**)&p_w, g_wimg);

    cudaFuncSetAttribute(gemm_tc<false, false>,
                         cudaFuncAttributeMaxDynamicSharedMemorySize, SMEM_G);
    cudaFuncSetAttribute(gemm_tc<true, false>,
                         cudaFuncAttributeMaxDynamicSharedMemorySize, SMEM_G);
    cudaFuncSetAttribute(gemm_tc<false, true>,
                         cudaFuncAttributeMaxDynamicSharedMemorySize, SMEM_G);
    cudaFuncSetAttribute(gemm_u1,
                         cudaFuncAttributeMaxDynamicSharedMemorySize, SMEM_G);

    const int GB = (Nn + 127) / 128;  // 391
#define IMG(i) (p_w + (i) * 65536)
#define GSUM(r) (p_gs + (r) * Gg * H)

    // setup
    zero_all_kernel<<<16, 256>>>();
    node_stats_kernel<<<(Nn + 255) / 256, 256>>>(batch, xm);
    edge_cnt_kernel<<<(Ee + 255) / 256, 256>>>(ei);
    wprep_kernel<<<512, 256>>>(W_e2, W_m1, W_m2, W_u1, W_u2, W_d1);

    // encoder
    enc1_kernel<<<(Nn * 32 + 255) / 256, 256>>>(x, xm, W_e1, b_e1);
    gemm_tc<false, false><<<GB, 512, SMEM_G>>>(p_t, IMG(0), b_e2, nullptr, p_h,
                                               nullptr, nullptr, Nn);

    group_sum_kernel<<<512, 128>>>(batch, xm, GSUM(0), 1);
    finalize_bc_kernel<<<Gg, 128>>>();

    for (int r = 0; r < REPEATS; r++) {
        fm_gvec_kernel<<<Gg, 128>>>(GSUM(r), W_u1, b_u1);
        // P = h @ W_src + b_m1
        gemm_tc<false, false><<<GB, 512, SMEM_G>>>(p_h, IMG(1), b_m1, nullptr,
                                                   p_P, nullptr, nullptr, Nn);
        // Q = h @ W_dst  (fused: R = relu(P + Q) self-loop init)
        gemm_tc<false, false><<<GB, 512, SMEM_G>>>(p_h, IMG(2), nullptr,
                                                   nullptr, p_Q, p_P, p_R, Nn);
        edge_msg_kernel<<<(Ee + 7) / 8, 256>>>(ei, ea, W_m1);
        // agg = (R @ W_m2) / cnt + b_m2
        gemm_tc<false, false><<<GB, 512, SMEM_G>>>(p_R, IMG(3), b_m2, p_cnt,
                                                   p_agg, nullptr, nullptr,
                                                   Nn);
        // t = relu(h@W4 + agg@W5 + gvec[batch])  (fused two-phase)
        gemm_u1<<<GB, 512, SMEM_G>>>(p_h, p_agg, IMG(4), IMG(5), p_gvec, batch,
                                     p_t, Nn);
        // h += t @ W_u2 + b_u2
        gemm_tc<false, true><<<GB, 512, SMEM_G>>>(p_t, IMG(6), b_u2, nullptr,
                                                  p_h, nullptr, nullptr, Nn);
        if (r < REPEATS - 1)
            group_sum_kernel<<<512, 128>>>(batch, xm, GSUM(r + 1), 0);
    }

    // decoder
    gemm_tc<true, false><<<GB, 512, SMEM_G>>>(p_h, IMG(7), b_d1, nullptr, p_t,
                                              nullptr, nullptr, Nn);
    dec2_kernel<<<(Nn + 7) / 8, 256>>>(W_d2, b_d2, out);
}

// round 12
// speedup vs baseline: 1.6777x; 1.6777x over previous
#include <cuda_runtime.h>
#include <cuda_bf16.h>
#include <math.h>
#include <stdint.h>

#define Nn 50000
#define Ee 400000
#define Gg 8
#define H  128
#define REPEATS 3
#define LDA 136

// ---------------- scratch (device globals; no allocation allowed) ----------
__device__ float g_h[Nn * H];
__device__ float g_t[Nn * H];
__device__ float g_P[Nn * H];
__device__ float g_Q[Nn * H];
__device__ float g_R[Nn * H];
__device__ float g_agg[Nn * H];
__device__ float g_cnt[Nn];
__device__ float g_gsum3[REPEATS][Gg * H];   // per-repeat sum buffers
__device__ float g_bcsum[Gg * H];
__device__ float g_xbc[Gg * H];
__device__ float g_gvec[Gg * H];
__device__ float g_gc[Gg];
__device__ float g_bccnt[Gg];
// pre-split bf16 weight images: 8 units x (32KB hi + 32KB lo), [n][k] layout
__device__ __align__(128) unsigned char g_wimg[8][65536];

// ---------------- mma/ldmatrix helpers (baseline PTX, sm_80+) ---------------
__device__ __forceinline__ uint32_t smem_u32(const void* p) {
    return (uint32_t)__cvta_generic_to_shared(p);
}
__device__ __forceinline__ void ldsm4(uint32_t* r, uint32_t addr) {
    asm volatile(
        "ldmatrix.sync.aligned.m8n8.x4.shared.b16 {%0,%1,%2,%3}, [%4];"
        : "=r"(r[0]), "=r"(r[1]), "=r"(r[2]), "=r"(r[3]) : "r"(addr));
}
__device__ __forceinline__ void mma16816(float* c, const uint32_t* a,
                                         uint32_t b0, uint32_t b1) {
    asm volatile(
        "mma.sync.aligned.m16n8k16.row.col.f32.bf16.bf16.f32 "
        "{%0,%1,%2,%3}, {%4,%5,%6,%7}, {%8,%9}, {%0,%1,%2,%3};"
        : "+f"(c[0]), "+f"(c[1]), "+f"(c[2]), "+f"(c[3])
        : "r"(a[0]), "r"(a[1]), "r"(a[2]), "r"(a[3]), "r"(b0), "r"(b1));
}

// ---------------- shared staging + compute helpers ---------------------------
// async B stage: issue cp.async for all 4096 16B chunks; caller must
// cp.async.wait_group 0 + __syncthreads() before use.
__device__ __forceinline__ void stage_B_async(
    const unsigned char* __restrict__ wimg, __nv_bfloat16* Bh,
    __nv_bfloat16* Bl, int tid) {
    const uint4* bsrc = (const uint4*)wimg;
#pragma unroll
    for (int i = 0; i < 8; i++) {
        int idx = i * 512 + tid;        // 4096 uint4 (hi then lo)
        int half = idx >> 11;
        int e = idx & 2047;
        int n = e >> 4, kc = (e & 15) * 8;
        __nv_bfloat16* dst = half ? Bl : Bh;
        uint32_t daddr = smem_u32(&dst[n * LDA + kc]);
        asm volatile("cp.async.cg.shared.global [%0], [%1], 16;"
                     :: "r"(daddr), "l"(bsrc + idx) : "memory");
    }
    asm volatile("cp.async.commit_group;" ::: "memory");
}
#define CPASYNC_WAIT() \
    asm volatile("cp.async.wait_group 0;" ::: "memory")

__device__ __forceinline__ void stage_A(const float* __restrict__ A,
                                        int rowBase, int M, __nv_bfloat16* Ah,
                                        __nv_bfloat16* Al, int tid) {
#pragma unroll
    for (int i = 0; i < 8; i++) {
        int fidx = i * 512 + tid;       // 4096 float4
        int r = fidx >> 5, c4 = (fidx & 31) * 4;
        float4 v = make_float4(0.f, 0.f, 0.f, 0.f);
        if (rowBase + r < M) v = *(const float4*)&A[(rowBase + r) * H + c4];
        unsigned short h0 = __bfloat16_as_ushort(__float2bfloat16(v.x));
        unsigned short h1 = __bfloat16_as_ushort(__float2bfloat16(v.y));
        unsigned short h2 = __bfloat16_as_ushort(__float2bfloat16(v.z));
        unsigned short h3 = __bfloat16_as_ushort(__float2bfloat16(v.w));
        float r0 = v.x - __bfloat162float(__ushort_as_bfloat16(h0));
        float r1 = v.y - __bfloat162float(__ushort_as_bfloat16(h1));
        float r2 = v.z - __bfloat162float(__ushort_as_bfloat16(h2));
        float r3 = v.w - __bfloat162float(__ushort_as_bfloat16(h3));
        unsigned short l0 = __bfloat16_as_ushort(__float2bfloat16(r0));
        unsigned short l1 = __bfloat16_as_ushort(__float2bfloat16(r1));
        unsigned short l2 = __bfloat16_as_ushort(__float2bfloat16(r2));
        unsigned short l3 = __bfloat16_as_ushort(__float2bfloat16(r3));
        uint2 hp = make_uint2((uint32_t)h0 | ((uint32_t)h1 << 16),
                              (uint32_t)h2 | ((uint32_t)h3 << 16));
        uint2 lp = make_uint2((uint32_t)l0 | ((uint32_t)l1 << 16),
                              (uint32_t)l2 | ((uint32_t)l3 << 16));
        *(uint2*)&Ah[r * LDA + c4] = hp;
        *(uint2*)&Al[r * LDA + c4] = lp;
    }
}

// D += Ah*Bh + Al*Bh + Ah*Bl (split-bf16 compensated product)
__device__ __forceinline__ void mma_3pass(const __nv_bfloat16* Ah,
                                          const __nv_bfloat16* Al,
                                          const __nv_bfloat16* Bh,
                                          const __nv_bfloat16* Bl, int aoff,
                                          int boff, float acc[2][4][4]) {
    const __nv_bfloat16* Aps[3] = {Ah, Al, Ah};
    const __nv_bfloat16* Bps[3] = {Bh, Bh, Bl};
#pragma unroll
    for (int pass = 0; pass < 3; pass++) {
        const __nv_bfloat16* Ab = Aps[pass];
        const __nv_bfloat16* Bb = Bps[pass];
#pragma unroll
        for (int kk = 0; kk < 8; kk++) {
            int k0 = kk * 16;
            uint32_t a[2][4], b[2][4];
#pragma unroll
            for (int mt = 0; mt < 2; mt++)
                ldsm4(a[mt], smem_u32(&Ab[aoff + mt * 16 * LDA + k0]));
#pragma unroll
            for (int np = 0; np < 2; np++)
                ldsm4(b[np], smem_u32(&Bb[boff + np * 16 * LDA + k0]));
#pragma unroll
            for (int mt = 0; mt < 2; mt++)
#pragma unroll
                for (int nt = 0; nt < 4; nt++)
                    mma16816(acc[mt][nt], a[mt], b[nt >> 1][(nt & 1) * 2],
                             b[nt >> 1][(nt & 1) * 2 + 1]);
        }
    }
}

// ---------------- weight prep: split f32 W[k][n] -> bf16 hi/lo [n][k] -------
__global__ void wprep_kernel(const float* __restrict__ We2,
                             const float* __restrict__ Wm1,
                             const float* __restrict__ Wm2,
                             const float* __restrict__ Wu1,
                             const float* __restrict__ Wu2,
                             const float* __restrict__ Wd1) {
    int unit = blockIdx.x >> 6;
    int t = (blockIdx.x & 63) * 256 + threadIdx.x;
    int n = t & 127, k = t >> 7;
    const float* src;
    switch (unit) {
        case 0: src = We2; break;
        case 1: src = Wm1; break;
        case 2: src = Wm1 + 128 * H; break;
        case 3: src = Wm2; break;
        case 4: src = Wu1; break;
        case 5: src = Wu1 + 128 * H; break;
        case 6: src = Wu2; break;
        default: src = Wd1; break;
    }
    float v = src[k * H + n];
    __nv_bfloat16 hb = __float2bfloat16(v);
    __nv_bfloat16 lb = __float2bfloat16(v - __bfloat162float(hb));
    unsigned short* img = (unsigned short*)(g_wimg[unit]);
    img[n * 128 + k] = __bfloat16_as_ushort(hb);
    img[16384 + n * 128 + k] = __bfloat16_as_ushort(lb);
}

// ---------------- R10 node GEMM: C[Mx128] = ep(A @ W), 128-row tiles --------
#define SMEM_G (4 * 128 * LDA * 2)
template <bool RELU, bool RESID>
__global__ __launch_bounds__(512, 1) void gemm_tc(
    const float* __restrict__ A, const unsigned char* __restrict__ wimg,
    const float* __restrict__ colbias, const float* __restrict__ rowdiv,
    float* __restrict__ C, const float* __restrict__ selfP,
    float* __restrict__ selfR, int M) {
    extern __shared__ __align__(16) unsigned char smem[];
    __nv_bfloat16* Ah = (__nv_bfloat16*)smem;
    __nv_bfloat16* Al = Ah + 128 * LDA;
    __nv_bfloat16* Bh = Al + 128 * LDA;
    __nv_bfloat16* Bl = Bh + 128 * LDA;
    int tid = threadIdx.x, lane = tid & 31, wid = tid >> 5;
    int rowBase = blockIdx.x * 128;

    stage_B_async(wimg, Bh, Bl, tid);   // B flows L2->smem async
    stage_A(A, rowBase, M, Ah, Al, tid);   // overlap: A LDG + cvt math
    CPASYNC_WAIT();
    __syncthreads();

    int warp_m = (wid & 3) * 32, warp_n = (wid >> 2) * 32;
    float acc[2][4][4];
#pragma unroll
    for (int mt = 0; mt < 2; mt++)
#pragma unroll
        for (int nt = 0; nt < 4; nt++)
#pragma unroll
            for (int q = 0; q < 4; q++) acc[mt][nt][q] = 0.f;

    int tq = lane >> 3, tr = lane & 7;
    int aoff = (warp_m + (tq & 1) * 8 + tr) * LDA + (tq >> 1) * 8;
    int boff = (warp_n + (tq >> 1) * 8 + tr) * LDA + (tq & 1) * 8;
    mma_3pass(Ah, Al, Bh, Bl, aoff, boff, acc);

#pragma unroll
    for (int mt = 0; mt < 2; mt++) {
#pragma unroll
        for (int half = 0; half < 2; half++) {
            int grow = rowBase + warp_m + mt * 16 + (lane >> 2) + half * 8;
            if (grow >= M) continue;
            float inv = 1.f;
            if (rowdiv) inv = 1.f / rowdiv[grow];
#pragma unroll
            for (int nt = 0; nt < 4; nt++) {
                int col = warp_n + nt * 8 + (lane & 3) * 2;
                float v0 = acc[mt][nt][half * 2 + 0];
                float v1 = acc[mt][nt][half * 2 + 1];
                if (rowdiv) { v0 *= inv; v1 *= inv; }
                if (colbias) { v0 += colbias[col]; v1 += colbias[col + 1]; }
                float* cp = &C[grow * H + col];
                if (RESID) {
                    float2 o = *(const float2*)cp;
                    v0 += o.x; v1 += o.y;
                }
                if (RELU) { v0 = fmaxf(v0, 0.f); v1 = fmaxf(v1, 0.f); }
                *(float2*)cp = make_float2(v0, v1);
                if (selfR) {
                    const float2 pp = *(const float2*)&selfP[grow * H + col];
                    *(float2*)&selfR[grow * H + col] =
                        make_float2(fmaxf(pp.x + v0, 0.f),
                                    fmaxf(pp.y + v1, 0.f));
                }
            }
        }
    }
}

// ---------------- fused update GEMM: t = relu(h@W4 + agg@W5 + gvec[batch]) --
__global__ __launch_bounds__(512, 1) void gemm_u1(
    const float* __restrict__ A1, const float* __restrict__ A2,
    const unsigned char* __restrict__ w4, const unsigned char* __restrict__ w5,
    const float* __restrict__ gvec, const int* __restrict__ batch,
    float* __restrict__ T, int M) {
    extern __shared__ __align__(16) unsigned char smem[];
    __nv_bfloat16* Ah = (__nv_bfloat16*)smem;
    __nv_bfloat16* Al = Ah + 128 * LDA;
    __nv_bfloat16* Bh = Al + 128 * LDA;
    __nv_bfloat16* Bl = Bh + 128 * LDA;
    int tid = threadIdx.x, lane = tid & 31, wid = tid >> 5;
    int rowBase = blockIdx.x * 128;

    int warp_m = (wid & 3) * 32, warp_n = (wid >> 2) * 32;
    float acc[2][4][4];
#pragma unroll
    for (int mt = 0; mt < 2; mt++)
#pragma unroll
        for (int nt = 0; nt < 4; nt++)
#pragma unroll
            for (int q = 0; q < 4; q++) acc[mt][nt][q] = 0.f;

    int tq = lane >> 3, tr = lane & 7;
    int aoff = (warp_m + (tq & 1) * 8 + tr) * LDA + (tq >> 1) * 8;
    int boff = (warp_n + (tq >> 1) * 8 + tr) * LDA + (tq & 1) * 8;

    // phase 1: h @ W4
    stage_B_async(w4, Bh, Bl, tid);
    stage_A(A1, rowBase, M, Ah, Al, tid);
    CPASYNC_WAIT();
    __syncthreads();
    mma_3pass(Ah, Al, Bh, Bl, aoff, boff, acc);
    __syncthreads();
    // phase 2: += agg @ W5
    stage_B_async(w5, Bh, Bl, tid);
    stage_A(A2, rowBase, M, Ah, Al, tid);
    CPASYNC_WAIT();
    __syncthreads();
    mma_3pass(Ah, Al, Bh, Bl, aoff, boff, acc);

#pragma unroll
    for (int mt = 0; mt < 2; mt++) {
#pragma unroll
        for (int half = 0; half < 2; half++) {
            int grow = rowBase + warp_m + mt * 16 + (lane >> 2) + half * 8;
            if (grow >= M) continue;
            const float* gv = &gvec[batch[grow] * H];
#pragma unroll
            for (int nt = 0; nt < 4; nt++) {
                int col = warp_n + nt * 8 + (lane & 3) * 2;
                float v0 = acc[mt][nt][half * 2 + 0] + gv[col];
                float v1 = acc[mt][nt][half * 2 + 1] + gv[col + 1];
                *(float2*)&T[grow * H + col] =
                    make_float2(fmaxf(v0, 0.f), fmaxf(v1, 0.f));
            }
        }
    }
}

// ---------------- small utility kernels ------------------------------------
__global__ void zero_all_kernel() {
    int i = blockIdx.x * 256 + threadIdx.x;   // grid 16 x 256 = 4096
    if (i < REPEATS * Gg * H) ((float*)g_gsum3)[i] = 0.f;
    if (i < Gg * H) g_bcsum[i] = 0.f;
    if (i < Gg) { g_gc[i] = 0.f; g_bccnt[i] = 0.f; }
}

__global__ void node_stats_kernel(const int* __restrict__ batch,
                                  const float* __restrict__ x_mask) {
    __shared__ float sgc[Gg], sbc[Gg];
    int tid = threadIdx.x;
    if (tid < Gg) { sgc[tid] = 0.f; sbc[tid] = 0.f; }
    __syncthreads();
    int n = blockIdx.x * 256 + tid;
    if (n < Nn) {
        int g = batch[n];
        float bc = x_mask[n * 3 + 2];
        atomicAdd(&sgc[g], 1.f);
        atomicAdd(&sbc[g], bc);
        g_cnt[n] = 1.f;
    }
    __syncthreads();
    if (tid < Gg) {
        atomicAdd(&g_gc[tid], sgc[tid]);
        atomicAdd(&g_bccnt[tid], sbc[tid]);
    }
}

__global__ void edge_cnt_kernel(const int* __restrict__ ei) {
    int e = blockIdx.x * 256 + threadIdx.x;
    if (e < Ee) atomicAdd(&g_cnt[ei[Ee + e]], 1.f);
}

__global__ void enc1_kernel(const float* __restrict__ x,
                            const float* __restrict__ xm,
                            const float* __restrict__ W_e1,
                            const float* __restrict__ b_e1) {
    __shared__ float Ws[8 * H];
    __shared__ float bs[H];
    int tid = threadIdx.x;
    for (int i = tid; i < 8 * H; i += 256) Ws[i] = W_e1[i];
    if (tid < H) bs[tid] = b_e1[tid];
    __syncthreads();
    int idx = blockIdx.x * 256 + tid;
    if (idx >= Nn * 32) return;
    int n = idx >> 5, j4 = (idx & 31) * 4;
    float in8[8];
#pragma unroll
    for (int k = 0; k < 5; k++) in8[k] = x[n * 5 + k];
#pragma unroll
    for (int k = 0; k < 3; k++) in8[5 + k] = xm[n * 3 + k];
    float4 acc = *(const float4*)&bs[j4];
#pragma unroll
    for (int k = 0; k < 8; k++) {
        float4 w = *(const float4*)&Ws[k * H + j4];
        acc.x = fmaf(in8[k], w.x, acc.x);
        acc.y = fmaf(in8[k], w.y, acc.y);
        acc.z = fmaf(in8[k], w.z, acc.z);
        acc.w = fmaf(in8[k], w.w, acc.w);
    }
    acc.x = fmaxf(acc.x, 0.f); acc.y = fmaxf(acc.y, 0.f);
    acc.z = fmaxf(acc.z, 0.f); acc.w = fmaxf(acc.w, 0.f);
    *(float4*)&g_t[n * H + j4] = acc;
}

__global__ __launch_bounds__(256) void edge_msg_kernel(
    const int* __restrict__ ei, const float* __restrict__ ea,
    const float* __restrict__ W_m1) {
    __shared__ float Wea[3 * H];
    int tid = threadIdx.x;
    for (int i = tid; i < 3 * H; i += 256) Wea[i] = W_m1[256 * H + i];
    __syncthreads();
    int e = blockIdx.x * 8 + (tid >> 5);
    if (e >= Ee) return;
    int lane = tid & 31;
    int src = ei[e];
    int dst = ei[Ee + e];
    float e0 = __ldg(&ea[e * 3 + 0]);
    float e1 = __ldg(&ea[e * 3 + 1]);
    float e2 = __ldg(&ea[e * 3 + 2]);
    int c = lane * 4;
    float4 p = *(const float4*)&g_P[src * H + c];
    float4 q = *(const float4*)&g_Q[dst * H + c];
    float4 w0 = *(const float4*)&Wea[0 * H + c];
    float4 w1 = *(const float4*)&Wea[1 * H + c];
    float4 w2 = *(const float4*)&Wea[2 * H + c];
    float vx = fmaxf(p.x + q.x + e0 * w0.x + e1 * w1.x + e2 * w2.x, 0.f);
    float vy = fmaxf(p.y + q.y + e0 * w0.y + e1 * w1.y + e2 * w2.y, 0.f);
    float vz = fmaxf(p.z + q.z + e0 * w0.z + e1 * w1.z + e2 * w2.z, 0.f);
    float vw = fmaxf(p.w + q.w + e0 * w0.w + e1 * w1.w + e2 * w2.w, 0.f);
    float* rp = &g_R[dst * H + c];
    asm volatile("red.global.add.v4.f32 [%0], {%1, %2, %3, %4};"
                 :: "l"(rp), "f"(vx), "f"(vy), "f"(vz), "f"(vw)
                 : "memory");
}

__global__ void group_sum_kernel(const int* __restrict__ batch,
                                 const float* __restrict__ x_mask,
                                 float* __restrict__ gsum, int withbc) {
    int j = threadIdx.x;
    int chunk = (Nn + gridDim.x - 1) / gridDim.x;
    int n0 = blockIdx.x * chunk;
    int n1 = n0 + chunk;
    if (n1 > Nn) n1 = Nn;
    if (n0 >= n1) return;
    float acc = 0.f, accb = 0.f;
    int gcur = batch[n0];
    for (int n = n0; n < n1; n++) {
        int g = batch[n];
        if (g != gcur) {
            atomicAdd(&gsum[gcur * H + j], acc);
            if (withbc) atomicAdd(&g_bcsum[gcur * H + j], accb);
            acc = 0.f; accb = 0.f; gcur = g;
        }
        float v = g_h[n * H + j];
        acc += v;
        if (withbc) accb += v * x_mask[n * 3 + 2];
    }
    atomicAdd(&gsum[gcur * H + j], acc);
    if (withbc) atomicAdd(&g_bcsum[gcur * H + j], accb);
}

__global__ void finalize_bc_kernel() {
    int g = blockIdx.x, j = threadIdx.x;
    float cb = fmaxf(g_bccnt[g], 1.f);
    g_xbc[g * H + j] = g_bcsum[g * H + j] / cb;
}

// gvec[g] = b_u1 + (gsum[g]/cnt) @ W_u1[256:384] + xbc[g] @ W_u1[384:512]
__global__ void fm_gvec_kernel(const float* __restrict__ gsum,
                               const float* __restrict__ W_u1,
                               const float* __restrict__ b_u1) {
    __shared__ float xg[H], xb[H];
    int g = blockIdx.x, j = threadIdx.x;
    float c = fmaxf(g_gc[g], 1.f);
    xg[j] = gsum[g * H + j] / c;
    xb[j] = g_xbc[g * H + j];
    __syncthreads();
    float acc = b_u1[j];
    for (int k = 0; k < H; k++) {
        acc = fmaf(xg[k], W_u1[(256 + k) * H + j], acc);
        acc = fmaf(xb[k], W_u1[(384 + k) * H + j], acc);
    }
    g_gvec[g * H + j] = acc;
}

__global__ void dec2_kernel(const float* __restrict__ W_d2,
                            const float* __restrict__ b_d2,
                            float* __restrict__ out) {
    int n = blockIdx.x * 8 + (threadIdx.x >> 5);
    if (n >= Nn) return;
    int lane = threadIdx.x & 31;
    float4 t4 = *(const float4*)&g_t[n * H + lane * 4];
    float tv[4] = {t4.x, t4.y, t4.z, t4.w};
    float a0 = 0.f, a1 = 0.f, a2 = 0.f;
#pragma unroll
    for (int r = 0; r < 4; r++) {
        int k = lane * 4 + r;
        a0 = fmaf(tv[r], __ldg(&W_d2[k * 3 + 0]), a0);
        a1 = fmaf(tv[r], __ldg(&W_d2[k * 3 + 1]), a1);
        a2 = fmaf(tv[r], __ldg(&W_d2[k * 3 + 2]), a2);
    }
#pragma unroll
    for (int off = 16; off; off >>= 1) {
        a0 += __shfl_down_sync(0xffffffffu, a0, off);
        a1 += __shfl_down_sync(0xffffffffu, a1, off);
        a2 += __shfl_down_sync(0xffffffffu, a2, off);
    }
    if (lane == 0) {
        out[n * 3 + 0] = a0 + b_d2[0];
        out[n * 3 + 1] = a1 + b_d2[1];
        out[n * 3 + 2] = a2 + b_d2[2];
    }
}

// ---------------- launch -----------------------------------------------------
extern "C" void kernel_launch(void* const* d_in, const int* in_sizes, int n_in,
                              void* d_out, int out_size) {
    const float* x    = (const float*)d_in[0];
    const float* xm   = (const float*)d_in[1];
    const float* ea   = (const float*)d_in[2];
    const float* W_e1 = (const float*)d_in[4];
    const float* b_e1 = (const float*)d_in[5];
    const float* W_e2 = (const float*)d_in[6];
    const float* b_e2 = (const float*)d_in[7];
    const float* W_m1 = (const float*)d_in[8];
    const float* b_m1 = (const float*)d_in[9];
    const float* W_m2 = (const float*)d_in[10];
    const float* b_m2 = (const float*)d_in[11];
    const float* W_u1 = (const float*)d_in[12];
    const float* b_u1 = (const float*)d_in[13];
    const float* W_u2 = (const float*)d_in[14];
    const float* b_u2 = (const float*)d_in[15];
    const float* W_d1 = (const float*)d_in[16];
    const float* b_d1 = (const float*)d_in[17];
    const float* W_d2 = (const float*)d_in[18];
    const float* b_d2 = (const float*)d_in[19];
    const int*   ei   = (const int*)d_in[20];
    const int*   batch = (const int*)d_in[21];
    float* out = (float*)d_out;

    float *p_h, *p_t, *p_P, *p_Q, *p_R, *p_agg, *p_cnt, *p_gvec, *p_gs;
    unsigned char* p_w;
    cudaGetSymbolAddress((void**)&p_h, g_h);
    cudaGetSymbolAddress((void**)&p_t, g_t);
    cudaGetSymbolAddress((void**)&p_P, g_P);
    cudaGetSymbolAddress((void**)&p_Q, g_Q);
    cudaGetSymbolAddress((void**)&p_R, g_R);
    cudaGetSymbolAddress((void**)&p_agg, g_agg);
    cudaGetSymbolAddress((void**)&p_cnt, g_cnt);
    cudaGetSymbolAddress((void**)&p_gvec, g_gvec);
    cudaGetSymbolAddress((void**)&p_gs, g_gsum3);
    cudaGetSymbolAddress((void**)&p_w, g_wimg);

    cudaFuncSetAttribute(gemm_tc<false, false>,
                         cudaFuncAttributeMaxDynamicSharedMemorySize, SMEM_G);
    cudaFuncSetAttribute(gemm_tc<true, false>,
                         cudaFuncAttributeMaxDynamicSharedMemorySize, SMEM_G);
    cudaFuncSetAttribute(gemm_tc<false, true>,
                         cudaFuncAttributeMaxDynamicSharedMemorySize, SMEM_G);
    cudaFuncSetAttribute(gemm_u1,
                         cudaFuncAttributeMaxDynamicSharedMemorySize, SMEM_G);

    const int GB = (Nn + 127) / 128;  // 391
#define IMG(i) (p_w + (i) * 65536)
#define GSUM(r) (p_gs + (r) * Gg * H)

    // setup
    zero_all_kernel<<<16, 256>>>();
    node_stats_kernel<<<(Nn + 255) / 256, 256>>>(batch, xm);
    edge_cnt_kernel<<<(Ee + 255) / 256, 256>>>(ei);
    wprep_kernel<<<512, 256>>>(W_e2, W_m1, W_m2, W_u1, W_u2, W_d1);

    // encoder
    enc1_kernel<<<(Nn * 32 + 255) / 256, 256>>>(x, xm, W_e1, b_e1);
    gemm_tc<false, false><<<GB, 512, SMEM_G>>>(p_t, IMG(0), b_e2, nullptr, p_h,
                                               nullptr, nullptr, Nn);

    group_sum_kernel<<<512, 128>>>(batch, xm, GSUM(0), 1);
    finalize_bc_kernel<<<Gg, 128>>>();

    for (int r = 0; r < REPEATS; r++) {
        fm_gvec_kernel<<<Gg, 128>>>(GSUM(r), W_u1, b_u1);
        // P = h @ W_src + b_m1
        gemm_tc<false, false><<<GB, 512, SMEM_G>>>(p_h, IMG(1), b_m1, nullptr,
                                                   p_P, nullptr, nullptr, Nn);
        // Q = h @ W_dst  (fused: R = relu(P + Q) self-loop init)
        gemm_tc<false, false><<<GB, 512, SMEM_G>>>(p_h, IMG(2), nullptr,
                                                   nullptr, p_Q, p_P, p_R, Nn);
        edge_msg_kernel<<<(Ee + 7) / 8, 256>>>(ei, ea, W_m1);
        // agg = (R @ W_m2) / cnt + b_m2
        gemm_tc<false, false><<<GB, 512, SMEM_G>>>(p_R, IMG(3), b_m2, p_cnt,
                                                   p_agg, nullptr, nullptr,
                                                   Nn);
        // t = relu(h@W4 + agg@W5 + gvec[batch])  (fused two-phase)
        gemm_u1<<<GB, 512, SMEM_G>>>(p_h, p_agg, IMG(4), IMG(5), p_gvec, batch,
                                     p_t, Nn);
        // h += t @ W_u2 + b_u2
        gemm_tc<false, true><<<GB, 512, SMEM_G>>>(p_t, IMG(6), b_u2, nullptr,
                                                  p_h, nullptr, nullptr, Nn);
        if (r < REPEATS - 1)
            group_sum_kernel<<<512, 128>>>(batch, xm, GSUM(r + 1), 0);
    }

    // decoder
    gemm_tc<true, false><<<GB, 512, SMEM_G>>>(p_h, IMG(7), b_d1, nullptr, p_t,
                                              nullptr, nullptr, Nn);
    dec2_kernel<<<(Nn + 7) / 8, 256>>>(W_d2, b_d2, out);
}

// round 13
// speedup vs baseline: 1.7365x; 1.0350x over previous
#include <cuda_runtime.h>
#include <cuda_bf16.h>
#include <math.h>
#include <stdint.h>

#define Nn 50000
#define Ee 400000
#define Gg 8
#define H  128
#define REPEATS 3
#define LDA 136

// ---------------- scratch (device globals; no allocation allowed) ----------
__device__ float g_h[Nn * H];
__device__ float g_t[Nn * H];
__device__ float g_P[Nn * H];
__device__ float g_Q[Nn * H];
__device__ float g_R[Nn * H];
__device__ float g_agg[Nn * H];
__device__ float g_cnt[Nn];
__device__ float g_gsum3[REPEATS][Gg * H];
__device__ float g_bcsum[Gg * H];
__device__ float g_xbc[Gg * H];
__device__ float g_gvec[Gg * H];
__device__ float g_gc[Gg];
__device__ float g_bccnt[Gg];
// CSR-by-dst (built once per launch in setup)
__device__ int g_deg[Nn];
__device__ int g_off[Nn + 1];
__device__ int g_fill[Nn];
__device__ int g_esrc[Ee];
__device__ int g_eidx[Ee];
// pre-split bf16 weight images: 8 units x (32KB hi + 32KB lo), [n][k] layout
__device__ __align__(128) unsigned char g_wimg[8][65536];

// ---------------- mma/ldmatrix helpers (baseline PTX, sm_80+) ---------------
__device__ __forceinline__ uint32_t smem_u32(const void* p) {
    return (uint32_t)__cvta_generic_to_shared(p);
}
__device__ __forceinline__ void ldsm4(uint32_t* r, uint32_t addr) {
    asm volatile(
        "ldmatrix.sync.aligned.m8n8.x4.shared.b16 {%0,%1,%2,%3}, [%4];"
        : "=r"(r[0]), "=r"(r[1]), "=r"(r[2]), "=r"(r[3]) : "r"(addr));
}
__device__ __forceinline__ void mma16816(float* c, const uint32_t* a,
                                         uint32_t b0, uint32_t b1) {
    asm volatile(
        "mma.sync.aligned.m16n8k16.row.col.f32.bf16.bf16.f32 "
        "{%0,%1,%2,%3}, {%4,%5,%6,%7}, {%8,%9}, {%0,%1,%2,%3};"
        : "+f"(c[0]), "+f"(c[1]), "+f"(c[2]), "+f"(c[3])
        : "r"(a[0]), "r"(a[1]), "r"(a[2]), "r"(a[3]), "r"(b0), "r"(b1));
}

// ---------------- staging + compute helpers (R10 baseline) ------------------
__device__ __forceinline__ void stage_B(const unsigned char* __restrict__ wimg,
                                        __nv_bfloat16* Bh, __nv_bfloat16* Bl,
                                        int tid) {
    const uint4* bsrc = (const uint4*)wimg;
#pragma unroll
    for (int i = 0; i < 8; i++) {
        int idx = i * 512 + tid;
        uint4 v = bsrc[idx];
        int half = idx >> 11;
        int e = idx & 2047;
        int n = e >> 4, kc = (e & 15) * 8;
        __nv_bfloat16* dst = half ? Bl : Bh;
        *(uint4*)&dst[n * LDA + kc] = v;
    }
}

__device__ __forceinline__ void stage_A(const float* __restrict__ A,
                                        int rowBase, int M, __nv_bfloat16* Ah,
                                        __nv_bfloat16* Al, int tid) {
#pragma unroll
    for (int i = 0; i < 8; i++) {
        int fidx = i * 512 + tid;
        int r = fidx >> 5, c4 = (fidx & 31) * 4;
        float4 v = make_float4(0.f, 0.f, 0.f, 0.f);
        if (rowBase + r < M) v = *(const float4*)&A[(rowBase + r) * H + c4];
        unsigned short h0 = __bfloat16_as_ushort(__float2bfloat16(v.x));
        unsigned short h1 = __bfloat16_as_ushort(__float2bfloat16(v.y));
        unsigned short h2 = __bfloat16_as_ushort(__float2bfloat16(v.z));
        unsigned short h3 = __bfloat16_as_ushort(__float2bfloat16(v.w));
        float r0 = v.x - __bfloat162float(__ushort_as_bfloat16(h0));
        float r1 = v.y - __bfloat162float(__ushort_as_bfloat16(h1));
        float r2 = v.z - __bfloat162float(__ushort_as_bfloat16(h2));
        float r3 = v.w - __bfloat162float(__ushort_as_bfloat16(h3));
        unsigned short l0 = __bfloat16_as_ushort(__float2bfloat16(r0));
        unsigned short l1 = __bfloat16_as_ushort(__float2bfloat16(r1));
        unsigned short l2 = __bfloat16_as_ushort(__float2bfloat16(r2));
        unsigned short l3 = __bfloat16_as_ushort(__float2bfloat16(r3));
        uint2 hp = make_uint2((uint32_t)h0 | ((uint32_t)h1 << 16),
                              (uint32_t)h2 | ((uint32_t)h3 << 16));
        uint2 lp = make_uint2((uint32_t)l0 | ((uint32_t)l1 << 16),
                              (uint32_t)l2 | ((uint32_t)l3 << 16));
        *(uint2*)&Ah[r * LDA + c4] = hp;
        *(uint2*)&Al[r * LDA + c4] = lp;
    }
}

__device__ __forceinline__ void mma_3pass(const __nv_bfloat16* Ah,
                                          const __nv_bfloat16* Al,
                                          const __nv_bfloat16* Bh,
                                          const __nv_bfloat16* Bl, int aoff,
                                          int boff, float acc[2][4][4]) {
    const __nv_bfloat16* Aps[3] = {Ah, Al, Ah};
    const __nv_bfloat16* Bps[3] = {Bh, Bh, Bl};
#pragma unroll
    for (int pass = 0; pass < 3; pass++) {
        const __nv_bfloat16* Ab = Aps[pass];
        const __nv_bfloat16* Bb = Bps[pass];
#pragma unroll
        for (int kk = 0; kk < 8; kk++) {
            int k0 = kk * 16;
            uint32_t a[2][4], b[2][4];
#pragma unroll
            for (int mt = 0; mt < 2; mt++)
                ldsm4(a[mt], smem_u32(&Ab[aoff + mt * 16 * LDA + k0]));
#pragma unroll
            for (int np = 0; np < 2; np++)
                ldsm4(b[np], smem_u32(&Bb[boff + np * 16 * LDA + k0]));
#pragma unroll
            for (int mt = 0; mt < 2; mt++)
#pragma unroll
                for (int nt = 0; nt < 4; nt++)
                    mma16816(acc[mt][nt], a[mt], b[nt >> 1][(nt & 1) * 2],
                             b[nt >> 1][(nt & 1) * 2 + 1]);
        }
    }
}

// ---------------- weight prep ------------------------------------------------
__global__ void wprep_kernel(const float* __restrict__ We2,
                             const float* __restrict__ Wm1,
                             const float* __restrict__ Wm2,
                             const float* __restrict__ Wu1,
                             const float* __restrict__ Wu2,
                             const float* __restrict__ Wd1) {
    int unit = blockIdx.x >> 6;
    int t = (blockIdx.x & 63) * 256 + threadIdx.x;
    int n = t & 127, k = t >> 7;
    const float* src;
    switch (unit) {
        case 0: src = We2; break;
        case 1: src = Wm1; break;
        case 2: src = Wm1 + 128 * H; break;
        case 3: src = Wm2; break;
        case 4: src = Wu1; break;
        case 5: src = Wu1 + 128 * H; break;
        case 6: src = Wu2; break;
        default: src = Wd1; break;
    }
    float v = src[k * H + n];
    __nv_bfloat16 hb = __float2bfloat16(v);
    __nv_bfloat16 lb = __float2bfloat16(v - __bfloat162float(hb));
    unsigned short* img = (unsigned short*)(g_wimg[unit]);
    img[n * 128 + k] = __bfloat16_as_ushort(hb);
    img[16384 + n * 128 + k] = __bfloat16_as_ushort(lb);
}

// ---------------- R10 node GEMM ---------------------------------------------
#define SMEM_G (4 * 128 * LDA * 2)
template <bool RELU, bool RESID>
__global__ __launch_bounds__(512, 1) void gemm_tc(
    const float* __restrict__ A, const unsigned char* __restrict__ wimg,
    const float* __restrict__ colbias, const float* __restrict__ rowdiv,
    float* __restrict__ C, int M) {
    extern __shared__ __align__(16) unsigned char smem[];
    __nv_bfloat16* Ah = (__nv_bfloat16*)smem;
    __nv_bfloat16* Al = Ah + 128 * LDA;
    __nv_bfloat16* Bh = Al + 128 * LDA;
    __nv_bfloat16* Bl = Bh + 128 * LDA;
    int tid = threadIdx.x, lane = tid & 31, wid = tid >> 5;
    int rowBase = blockIdx.x * 128;

    stage_B(wimg, Bh, Bl, tid);
    stage_A(A, rowBase, M, Ah, Al, tid);
    __syncthreads();

    int warp_m = (wid & 3) * 32, warp_n = (wid >> 2) * 32;
    float acc[2][4][4];
#pragma unroll
    for (int mt = 0; mt < 2; mt++)
#pragma unroll
        for (int nt = 0; nt < 4; nt++)
#pragma unroll
            for (int q = 0; q < 4; q++) acc[mt][nt][q] = 0.f;

    int tq = lane >> 3, tr = lane & 7;
    int aoff = (warp_m + (tq & 1) * 8 + tr) * LDA + (tq >> 1) * 8;
    int boff = (warp_n + (tq >> 1) * 8 + tr) * LDA + (tq & 1) * 8;
    mma_3pass(Ah, Al, Bh, Bl, aoff, boff, acc);

#pragma unroll
    for (int mt = 0; mt < 2; mt++) {
#pragma unroll
        for (int half = 0; half < 2; half++) {
            int grow = rowBase + warp_m + mt * 16 + (lane >> 2) + half * 8;
            if (grow >= M) continue;
            float inv = 1.f;
            if (rowdiv) inv = 1.f / rowdiv[grow];
#pragma unroll
            for (int nt = 0; nt < 4; nt++) {
                int col = warp_n + nt * 8 + (lane & 3) * 2;
                float v0 = acc[mt][nt][half * 2 + 0];
                float v1 = acc[mt][nt][half * 2 + 1];
                if (rowdiv) { v0 *= inv; v1 *= inv; }
                if (colbias) { v0 += colbias[col]; v1 += colbias[col + 1]; }
                float* cp = &C[grow * H + col];
                if (RESID) {
                    float2 o = *(const float2*)cp;
                    v0 += o.x; v1 += o.y;
                }
                if (RELU) { v0 = fmaxf(v0, 0.f); v1 = fmaxf(v1, 0.f); }
                *(float2*)cp = make_float2(v0, v1);
            }
        }
    }
}

// ---------------- fused update GEMM ------------------------------------------
__global__ __launch_bounds__(512, 1) void gemm_u1(
    const float* __restrict__ A1, const float* __restrict__ A2,
    const unsigned char* __restrict__ w4, const unsigned char* __restrict__ w5,
    const float* __restrict__ gvec, const int* __restrict__ batch,
    float* __restrict__ T, int M) {
    extern __shared__ __align__(16) unsigned char smem[];
    __nv_bfloat16* Ah = (__nv_bfloat16*)smem;
    __nv_bfloat16* Al = Ah + 128 * LDA;
    __nv_bfloat16* Bh = Al + 128 * LDA;
    __nv_bfloat16* Bl = Bh + 128 * LDA;
    int tid = threadIdx.x, lane = tid & 31, wid = tid >> 5;
    int rowBase = blockIdx.x * 128;

    int warp_m = (wid & 3) * 32, warp_n = (wid >> 2) * 32;
    float acc[2][4][4];
#pragma unroll
    for (int mt = 0; mt < 2; mt++)
#pragma unroll
        for (int nt = 0; nt < 4; nt++)
#pragma unroll
            for (int q = 0; q < 4; q++) acc[mt][nt][q] = 0.f;

    int tq = lane >> 3, tr = lane & 7;
    int aoff = (warp_m + (tq & 1) * 8 + tr) * LDA + (tq >> 1) * 8;
    int boff = (warp_n + (tq >> 1) * 8 + tr) * LDA + (tq & 1) * 8;

    stage_B(w4, Bh, Bl, tid);
    stage_A(A1, rowBase, M, Ah, Al, tid);
    __syncthreads();
    mma_3pass(Ah, Al, Bh, Bl, aoff, boff, acc);
    __syncthreads();
    stage_B(w5, Bh, Bl, tid);
    stage_A(A2, rowBase, M, Ah, Al, tid);
    __syncthreads();
    mma_3pass(Ah, Al, Bh, Bl, aoff, boff, acc);

#pragma unroll
    for (int mt = 0; mt < 2; mt++) {
#pragma unroll
        for (int half = 0; half < 2; half++) {
            int grow = rowBase + warp_m + mt * 16 + (lane >> 2) + half * 8;
            if (grow >= M) continue;
            const float* gv = &gvec[batch[grow] * H];
#pragma unroll
            for (int nt = 0; nt < 4; nt++) {
                int col = warp_n + nt * 8 + (lane & 3) * 2;
                float v0 = acc[mt][nt][half * 2 + 0] + gv[col];
                float v1 = acc[mt][nt][half * 2 + 1] + gv[col + 1];
                *(float2*)&T[grow * H + col] =
                    make_float2(fmaxf(v0, 0.f), fmaxf(v1, 0.f));
            }
        }
    }
}

// ---------------- setup: zero, stats, CSR build ------------------------------
__global__ void zero_all_kernel() {
    int i = blockIdx.x * 256 + threadIdx.x;   // grid covers Nn
    if (i < Nn) g_deg[i] = 0;
    if (i < REPEATS * Gg * H) ((float*)g_gsum3)[i] = 0.f;
    if (i < Gg * H) g_bcsum[i] = 0.f;
    if (i < Gg) { g_gc[i] = 0.f; g_bccnt[i] = 0.f; }
}

__global__ void node_stats_kernel(const int* __restrict__ batch,
                                  const float* __restrict__ x_mask) {
    __shared__ float sgc[Gg], sbc[Gg];
    int tid = threadIdx.x;
    if (tid < Gg) { sgc[tid] = 0.f; sbc[tid] = 0.f; }
    __syncthreads();
    int n = blockIdx.x * 256 + tid;
    if (n < Nn) {
        int g = batch[n];
        atomicAdd(&sgc[g], 1.f);
        atomicAdd(&sbc[g], x_mask[n * 3 + 2]);
    }
    __syncthreads();
    if (tid < Gg) {
        atomicAdd(&g_gc[tid], sgc[tid]);
        atomicAdd(&g_bccnt[tid], sbc[tid]);
    }
}

__global__ void hist_kernel(const int* __restrict__ ei) {
    int e = blockIdx.x * 256 + threadIdx.x;
    if (e < Ee) atomicAdd(&g_deg[ei[Ee + e]], 1);
}

// single-block exclusive scan over g_deg -> g_off; also g_cnt, g_fill
__global__ __launch_bounds__(1024) void scan_kernel() {
    __shared__ int psum[1024];
    int tid = threadIdx.x;
    const int CH = (Nn + 1023) / 1024;  // 49
    int n0 = tid * CH, n1 = n0 + CH;
    if (n1 > Nn) n1 = Nn;
    int s = 0;
    for (int n = n0; n < n1; n++) s += g_deg[n];
    psum[tid] = s;
    __syncthreads();
    for (int off = 1; off < 1024; off <<= 1) {
        int v = (tid >= off) ? psum[tid - off] : 0;
        __syncthreads();
        psum[tid] += v;
        __syncthreads();
    }
    int base = (tid == 0) ? 0 : psum[tid - 1];
    for (int n = n0; n < n1; n++) {
        g_off[n] = base;
        int d = g_deg[n];
        base += d;
        g_cnt[n] = (float)(d + 1);   // +1 self loop
        g_fill[n] = 0;
    }
    if (tid == 0) g_off[Nn] = psum[1023];
}

__global__ void scatter_kernel(const int* __restrict__ ei) {
    int e = blockIdx.x * 256 + threadIdx.x;
    if (e >= Ee) return;
    int dst = ei[Ee + e];
    int pos = g_off[dst] + atomicAdd(&g_fill[dst], 1);
    g_esrc[pos] = ei[e];
    g_eidx[pos] = e;
}

// ---------------- encoder layer 1 --------------------------------------------
__global__ void enc1_kernel(const float* __restrict__ x,
                            const float* __restrict__ xm,
                            const float* __restrict__ W_e1,
                            const float* __restrict__ b_e1) {
    __shared__ float Ws[8 * H];
    __shared__ float bs[H];
    int tid = threadIdx.x;
    for (int i = tid; i < 8 * H; i += 256) Ws[i] = W_e1[i];
    if (tid < H) bs[tid] = b_e1[tid];
    __syncthreads();
    int idx = blockIdx.x * 256 + tid;
    if (idx >= Nn * 32) return;
    int n = idx >> 5, j4 = (idx & 31) * 4;
    float in8[8];
#pragma unroll
    for (int k = 0; k < 5; k++) in8[k] = x[n * 5 + k];
#pragma unroll
    for (int k = 0; k < 3; k++) in8[5 + k] = xm[n * 3 + k];
    float4 acc = *(const float4*)&bs[j4];
#pragma unroll
    for (int k = 0; k < 8; k++) {
        float4 w = *(const float4*)&Ws[k * H + j4];
        acc.x = fmaf(in8[k], w.x, acc.x);
        acc.y = fmaf(in8[k], w.y, acc.y);
        acc.z = fmaf(in8[k], w.z, acc.z);
        acc.w = fmaf(in8[k], w.w, acc.w);
    }
    acc.x = fmaxf(acc.x, 0.f); acc.y = fmaxf(acc.y, 0.f);
    acc.z = fmaxf(acc.z, 0.f); acc.w = fmaxf(acc.w, 0.f);
    *(float4*)&g_t[n * H + j4] = acc;
}

// ---------------- CSR edge kernel: one warp per dst node ---------------------
// R[dst] = relu(P[dst]+Q[dst]) + sum_e relu(P[src]+Q[dst]+ea@Wea)
__global__ __launch_bounds__(256) void edge_csr_kernel(
    const float* __restrict__ ea, const float* __restrict__ W_m1) {
    __shared__ float Wea[3 * H];
    int tid = threadIdx.x;
    for (int i = tid; i < 3 * H; i += 256) Wea[i] = W_m1[256 * H + i];
    __syncthreads();
    int node = blockIdx.x * 8 + (tid >> 5);
    if (node >= Nn) return;
    int lane = tid & 31;
    int c = lane * 4;
    float4 qd = *(const float4*)&g_Q[node * H + c];
    float4 pd = *(const float4*)&g_P[node * H + c];
    float4 acc;
    acc.x = fmaxf(pd.x + qd.x, 0.f);
    acc.y = fmaxf(pd.y + qd.y, 0.f);
    acc.z = fmaxf(pd.z + qd.z, 0.f);
    acc.w = fmaxf(pd.w + qd.w, 0.f);
    float4 w0 = *(const float4*)&Wea[0 * H + c];
    float4 w1 = *(const float4*)&Wea[1 * H + c];
    float4 w2 = *(const float4*)&Wea[2 * H + c];
    int p0 = g_off[node], p1 = g_off[node + 1];
    for (int p = p0; p < p1; p++) {
        int src = g_esrc[p];
        int e = g_eidx[p];
        float e0 = __ldg(&ea[e * 3 + 0]);
        float e1 = __ldg(&ea[e * 3 + 1]);
        float e2 = __ldg(&ea[e * 3 + 2]);
        float4 ps = *(const float4*)&g_P[src * H + c];
        acc.x += fmaxf(ps.x + qd.x + e0 * w0.x + e1 * w1.x + e2 * w2.x, 0.f);
        acc.y += fmaxf(ps.y + qd.y + e0 * w0.y + e1 * w1.y + e2 * w2.y, 0.f);
        acc.z += fmaxf(ps.z + qd.z + e0 * w0.z + e1 * w1.z + e2 * w2.z, 0.f);
        acc.w += fmaxf(ps.w + qd.w + e0 * w0.w + e1 * w1.w + e2 * w2.w, 0.f);
    }
    *(float4*)&g_R[node * H + c] = acc;
}

// ---------------- group stats ------------------------------------------------
__global__ void group_sum_kernel(const int* __restrict__ batch,
                                 const float* __restrict__ x_mask,
                                 float* __restrict__ gsum, int withbc) {
    int j = threadIdx.x;
    int chunk = (Nn + gridDim.x - 1) / gridDim.x;
    int n0 = blockIdx.x * chunk;
    int n1 = n0 + chunk;
    if (n1 > Nn) n1 = Nn;
    if (n0 >= n1) return;
    float acc = 0.f, accb = 0.f;
    int gcur = batch[n0];
    for (int n = n0; n < n1; n++) {
        int g = batch[n];
        if (g != gcur) {
            atomicAdd(&gsum[gcur * H + j], acc);
            if (withbc) atomicAdd(&g_bcsum[gcur * H + j], accb);
            acc = 0.f; accb = 0.f; gcur = g;
        }
        float v = g_h[n * H + j];
        acc += v;
        if (withbc) accb += v * x_mask[n * 3 + 2];
    }
    atomicAdd(&gsum[gcur * H + j], acc);
    if (withbc) atomicAdd(&g_bcsum[gcur * H + j], accb);
}

__global__ void finalize_bc_kernel() {
    int g = blockIdx.x, j = threadIdx.x;
    float cb = fmaxf(g_bccnt[g], 1.f);
    g_xbc[g * H + j] = g_bcsum[g * H + j] / cb;
}

__global__ void fm_gvec_kernel(const float* __restrict__ gsum,
                               const float* __restrict__ W_u1,
                               const float* __restrict__ b_u1) {
    __shared__ float xg[H], xb[H];
    int g = blockIdx.x, j = threadIdx.x;
    float c = fmaxf(g_gc[g], 1.f);
    xg[j] = gsum[g * H + j] / c;
    xb[j] = g_xbc[g * H + j];
    __syncthreads();
    float acc = b_u1[j];
    for (int k = 0; k < H; k++) {
        acc = fmaf(xg[k], W_u1[(256 + k) * H + j], acc);
        acc = fmaf(xb[k], W_u1[(384 + k) * H + j], acc);
    }
    g_gvec[g * H + j] = acc;
}

__global__ void dec2_kernel(const float* __restrict__ W_d2,
                            const float* __restrict__ b_d2,
                            float* __restrict__ out) {
    int n = blockIdx.x * 8 + (threadIdx.x >> 5);
    if (n >= Nn) return;
    int lane = threadIdx.x & 31;
    float4 t4 = *(const float4*)&g_t[n * H + lane * 4];
    float tv[4] = {t4.x, t4.y, t4.z, t4.w};
    float a0 = 0.f, a1 = 0.f, a2 = 0.f;
#pragma unroll
    for (int r = 0; r < 4; r++) {
        int k = lane * 4 + r;
        a0 = fmaf(tv[r], __ldg(&W_d2[k * 3 + 0]), a0);
        a1 = fmaf(tv[r], __ldg(&W_d2[k * 3 + 1]), a1);
        a2 = fmaf(tv[r], __ldg(&W_d2[k * 3 + 2]), a2);
    }
#pragma unroll
    for (int off = 16; off; off >>= 1) {
        a0 += __shfl_down_sync(0xffffffffu, a0, off);
        a1 += __shfl_down_sync(0xffffffffu, a1, off);
        a2 += __shfl_down_sync(0xffffffffu, a2, off);
    }
    if (lane == 0) {
        out[n * 3 + 0] = a0 + b_d2[0];
        out[n * 3 + 1] = a1 + b_d2[1];
        out[n * 3 + 2] = a2 + b_d2[2];
    }
}

// ---------------- launch -----------------------------------------------------
extern "C" void kernel_launch(void* const* d_in, const int* in_sizes, int n_in,
                              void* d_out, int out_size) {
    const float* x    = (const float*)d_in[0];
    const float* xm   = (const float*)d_in[1];
    const float* ea   = (const float*)d_in[2];
    const float* W_e1 = (const float*)d_in[4];
    const float* b_e1 = (const float*)d_in[5];
    const float* W_e2 = (const float*)d_in[6];
    const float* b_e2 = (const float*)d_in[7];
    const float* W_m1 = (const float*)d_in[8];
    const float* b_m1 = (const float*)d_in[9];
    const float* W_m2 = (const float*)d_in[10];
    const float* b_m2 = (const float*)d_in[11];
    const float* W_u1 = (const float*)d_in[12];
    const float* b_u1 = (const float*)d_in[13];
    const float* W_u2 = (const float*)d_in[14];
    const float* b_u2 = (const float*)d_in[15];
    const float* W_d1 = (const float*)d_in[16];
    const float* b_d1 = (const float*)d_in[17];
    const float* W_d2 = (const float*)d_in[18];
    const float* b_d2 = (const float*)d_in[19];
    const int*   ei   = (const int*)d_in[20];
    const int*   batch = (const int*)d_in[21];
    float* out = (float*)d_out;

    float *p_h, *p_t, *p_P, *p_Q, *p_R, *p_agg, *p_cnt, *p_gvec, *p_gs;
    unsigned char* p_w;
    cudaGetSymbolAddress((void**)&p_h, g_h);
    cudaGetSymbolAddress((void**)&p_t, g_t);
    cudaGetSymbolAddress((void**)&p_P, g_P);
    cudaGetSymbolAddress((void**)&p_Q, g_Q);
    cudaGetSymbolAddress((void**)&p_R, g_R);
    cudaGetSymbolAddress((void**)&p_agg, g_agg);
    cudaGetSymbolAddress((void**)&p_cnt, g_cnt);
    cudaGetSymbolAddress((void**)&p_gvec, g_gvec);
    cudaGetSymbolAddress((void**)&p_gs, g_gsum3);
    cudaGetSymbolAddress((void**)&p_w, g_wimg);

    cudaFuncSetAttribute(gemm_tc<false, false>,
                         cudaFuncAttributeMaxDynamicSharedMemorySize, SMEM_G);
    cudaFuncSetAttribute(gemm_tc<true, false>,
                         cudaFuncAttributeMaxDynamicSharedMemorySize, SMEM_G);
    cudaFuncSetAttribute(gemm_tc<false, true>,
                         cudaFuncAttributeMaxDynamicSharedMemorySize, SMEM_G);
    cudaFuncSetAttribute(gemm_u1,
                         cudaFuncAttributeMaxDynamicSharedMemorySize, SMEM_G);

    const int GB = (Nn + 127) / 128;  // 391
#define IMG(i) (p_w + (i) * 65536)
#define GSUM(r) (p_gs + (r) * Gg * H)

    // setup + CSR build (edge_index constant across replays but rebuilt each
    // call for determinism under graph capture)
    zero_all_kernel<<<(Nn + 255) / 256, 256>>>();
    node_stats_kernel<<<(Nn + 255) / 256, 256>>>(batch, xm);
    hist_kernel<<<(Ee + 255) / 256, 256>>>(ei);
    scan_kernel<<<1, 1024>>>();
    scatter_kernel<<<(Ee + 255) / 256, 256>>>(ei);
    wprep_kernel<<<512, 256>>>(W_e2, W_m1, W_m2, W_u1, W_u2, W_d1);

    // encoder
    enc1_kernel<<<(Nn * 32 + 255) / 256, 256>>>(x, xm, W_e1, b_e1);
    gemm_tc<false, false><<<GB, 512, SMEM_G>>>(p_t, IMG(0), b_e2, nullptr, p_h,
                                               Nn);

    group_sum_kernel<<<512, 128>>>(batch, xm, GSUM(0), 1);
    finalize_bc_kernel<<<Gg, 128>>>();

    for (int r = 0; r < REPEATS; r++) {
        fm_gvec_kernel<<<Gg, 128>>>(GSUM(r), W_u1, b_u1);
        // P = h @ W_src + b_m1 ; Q = h @ W_dst
        gemm_tc<false, false><<<GB, 512, SMEM_G>>>(p_h, IMG(1), b_m1, nullptr,
                                                   p_P, Nn);
        gemm_tc<false, false><<<GB, 512, SMEM_G>>>(p_h, IMG(2), nullptr,
                                                   nullptr, p_Q, Nn);
        // R[dst] = selfloop + sum over CSR edge list (no atomics)
        edge_csr_kernel<<<(Nn + 7) / 8, 256>>>(ea, W_m1);
        // agg = (R @ W_m2) / cnt + b_m2
        gemm_tc<false, false><<<GB, 512, SMEM_G>>>(p_R, IMG(3), b_m2, p_cnt,
                                                   p_agg, Nn);
        // t = relu(h@W4 + agg@W5 + gvec[batch])
        gemm_u1<<<GB, 512, SMEM_G>>>(p_h, p_agg, IMG(4), IMG(5), p_gvec, batch,
                                     p_t, Nn);
        // h += t @ W_u2 + b_u2
        gemm_tc<false, true><<<GB, 512, SMEM_G>>>(p_t, IMG(6), b_u2, nullptr,
                                                  p_h, Nn);
        if (r < REPEATS - 1)
            group_sum_kernel<<<512, 128>>>(batch, xm, GSUM(r + 1), 0);
    }

    // decoder
    gemm_tc<true, false><<<GB, 512, SMEM_G>>>(p_h, IMG(7), b_d1, nullptr, p_t,
                                              Nn);
    dec2_kernel<<<(Nn + 7) / 8, 256>>>(W_d2, b_d2, out);
}

// round 14
// speedup vs baseline: 1.9136x; 1.1020x over previous
#include <cuda_runtime.h>
#include <cuda_bf16.h>
#include <math.h>
#include <stdint.h>

#define Nn 50000
#define Ee 400000
#define Gg 8
#define H  128
#define REPEATS 3
#define LDA 136
#define NB ((Nn + 255) / 256)   // 196 scan blocks

// ---------------- scratch (device globals; no allocation allowed) ----------
__device__ float g_h[Nn * H];
__device__ float g_t[Nn * H];
__device__ float g_P[Nn * H];
__device__ float g_Q[Nn * H];
__device__ float g_R[Nn * H];
__device__ float g_agg[Nn * H];
__device__ float g_cnt[Nn];
__device__ float g_gsum3[REPEATS][Gg * H];
__device__ float g_bcsum[Gg * H];
__device__ float g_xbc[Gg * H];
__device__ float g_gvec[Gg * H];
__device__ float g_gc[Gg];
__device__ float g_bccnt[Gg];
// CSR-by-dst (built once per launch in setup)
__device__ int g_deg[Nn];
__device__ int g_off[Nn + 1];
__device__ int g_fill[Nn];
__device__ int g_esrc[Ee];
__device__ int g_eidx[Ee];
__device__ int g_bsum[256];
// pre-split bf16 weight images: 8 units x (32KB hi + 32KB lo), [n][k] layout
__device__ __align__(128) unsigned char g_wimg[8][65536];

// ---------------- mma/ldmatrix helpers (baseline PTX, sm_80+) ---------------
__device__ __forceinline__ uint32_t smem_u32(const void* p) {
    return (uint32_t)__cvta_generic_to_shared(p);
}
__device__ __forceinline__ void ldsm4(uint32_t* r, uint32_t addr) {
    asm volatile(
        "ldmatrix.sync.aligned.m8n8.x4.shared.b16 {%0,%1,%2,%3}, [%4];"
        : "=r"(r[0]), "=r"(r[1]), "=r"(r[2]), "=r"(r[3]) : "r"(addr));
}
__device__ __forceinline__ void mma16816(float* c, const uint32_t* a,
                                         uint32_t b0, uint32_t b1) {
    asm volatile(
        "mma.sync.aligned.m16n8k16.row.col.f32.bf16.bf16.f32 "
        "{%0,%1,%2,%3}, {%4,%5,%6,%7}, {%8,%9}, {%0,%1,%2,%3};"
        : "+f"(c[0]), "+f"(c[1]), "+f"(c[2]), "+f"(c[3])
        : "r"(a[0]), "r"(a[1]), "r"(a[2]), "r"(a[3]), "r"(b0), "r"(b1));
}

// ---------------- staging + compute helpers (R10 baseline) ------------------
__device__ __forceinline__ void stage_B(const unsigned char* __restrict__ wimg,
                                        __nv_bfloat16* Bh, __nv_bfloat16* Bl,
                                        int tid) {
    const uint4* bsrc = (const uint4*)wimg;
#pragma unroll
    for (int i = 0; i < 8; i++) {
        int idx = i * 512 + tid;
        uint4 v = bsrc[idx];
        int half = idx >> 11;
        int e = idx & 2047;
        int n = e >> 4, kc = (e & 15) * 8;
        __nv_bfloat16* dst = half ? Bl : Bh;
        *(uint4*)&dst[n * LDA + kc] = v;
    }
}

__device__ __forceinline__ void stage_A(const float* __restrict__ A,
                                        int rowBase, int M, __nv_bfloat16* Ah,
                                        __nv_bfloat16* Al, int tid) {
#pragma unroll
    for (int i = 0; i < 8; i++) {
        int fidx = i * 512 + tid;
        int r = fidx >> 5, c4 = (fidx & 31) * 4;
        float4 v = make_float4(0.f, 0.f, 0.f, 0.f);
        if (rowBase + r < M) v = *(const float4*)&A[(rowBase + r) * H + c4];
        unsigned short h0 = __bfloat16_as_ushort(__float2bfloat16(v.x));
        unsigned short h1 = __bfloat16_as_ushort(__float2bfloat16(v.y));
        unsigned short h2 = __bfloat16_as_ushort(__float2bfloat16(v.z));
        unsigned short h3 = __bfloat16_as_ushort(__float2bfloat16(v.w));
        float r0 = v.x - __bfloat162float(__ushort_as_bfloat16(h0));
        float r1 = v.y - __bfloat162float(__ushort_as_bfloat16(h1));
        float r2 = v.z - __bfloat162float(__ushort_as_bfloat16(h2));
        float r3 = v.w - __bfloat162float(__ushort_as_bfloat16(h3));
        unsigned short l0 = __bfloat16_as_ushort(__float2bfloat16(r0));
        unsigned short l1 = __bfloat16_as_ushort(__float2bfloat16(r1));
        unsigned short l2 = __bfloat16_as_ushort(__float2bfloat16(r2));
        unsigned short l3 = __bfloat16_as_ushort(__float2bfloat16(r3));
        uint2 hp = make_uint2((uint32_t)h0 | ((uint32_t)h1 << 16),
                              (uint32_t)h2 | ((uint32_t)h3 << 16));
        uint2 lp = make_uint2((uint32_t)l0 | ((uint32_t)l1 << 16),
                              (uint32_t)l2 | ((uint32_t)l3 << 16));
        *(uint2*)&Ah[r * LDA + c4] = hp;
        *(uint2*)&Al[r * LDA + c4] = lp;
    }
}

__device__ __forceinline__ void mma_3pass(const __nv_bfloat16* Ah,
                                          const __nv_bfloat16* Al,
                                          const __nv_bfloat16* Bh,
                                          const __nv_bfloat16* Bl, int aoff,
                                          int boff, float acc[2][4][4]) {
    const __nv_bfloat16* Aps[3] = {Ah, Al, Ah};
    const __nv_bfloat16* Bps[3] = {Bh, Bh, Bl};
#pragma unroll
    for (int pass = 0; pass < 3; pass++) {
        const __nv_bfloat16* Ab = Aps[pass];
        const __nv_bfloat16* Bb = Bps[pass];
#pragma unroll
        for (int kk = 0; kk < 8; kk++) {
            int k0 = kk * 16;
            uint32_t a[2][4], b[2][4];
#pragma unroll
            for (int mt = 0; mt < 2; mt++)
                ldsm4(a[mt], smem_u32(&Ab[aoff + mt * 16 * LDA + k0]));
#pragma unroll
            for (int np = 0; np < 2; np++)
                ldsm4(b[np], smem_u32(&Bb[boff + np * 16 * LDA + k0]));
#pragma unroll
            for (int mt = 0; mt < 2; mt++)
#pragma unroll
                for (int nt = 0; nt < 4; nt++)
                    mma16816(acc[mt][nt], a[mt], b[nt >> 1][(nt & 1) * 2],
                             b[nt >> 1][(nt & 1) * 2 + 1]);
        }
    }
}

// ---------------- weight prep ------------------------------------------------
__global__ void wprep_kernel(const float* __restrict__ We2,
                             const float* __restrict__ Wm1,
                             const float* __restrict__ Wm2,
                             const float* __restrict__ Wu1,
                             const float* __restrict__ Wu2,
                             const float* __restrict__ Wd1) {
    int unit = blockIdx.x >> 6;
    int t = (blockIdx.x & 63) * 256 + threadIdx.x;
    int n = t & 127, k = t >> 7;
    const float* src;
    switch (unit) {
        case 0: src = We2; break;
        case 1: src = Wm1; break;
        case 2: src = Wm1 + 128 * H; break;
        case 3: src = Wm2; break;
        case 4: src = Wu1; break;
        case 5: src = Wu1 + 128 * H; break;
        case 6: src = Wu2; break;
        default: src = Wd1; break;
    }
    float v = src[k * H + n];
    __nv_bfloat16 hb = __float2bfloat16(v);
    __nv_bfloat16 lb = __float2bfloat16(v - __bfloat162float(hb));
    unsigned short* img = (unsigned short*)(g_wimg[unit]);
    img[n * 128 + k] = __bfloat16_as_ushort(hb);
    img[16384 + n * 128 + k] = __bfloat16_as_ushort(lb);
}

// ---------------- R10 node GEMM ---------------------------------------------
#define SMEM_G (4 * 128 * LDA * 2)
template <bool RELU, bool RESID>
__global__ __launch_bounds__(512, 1) void gemm_tc(
    const float* __restrict__ A, const unsigned char* __restrict__ wimg,
    const float* __restrict__ colbias, const float* __restrict__ rowdiv,
    float* __restrict__ C, int M) {
    extern __shared__ __align__(16) unsigned char smem[];
    __nv_bfloat16* Ah = (__nv_bfloat16*)smem;
    __nv_bfloat16* Al = Ah + 128 * LDA;
    __nv_bfloat16* Bh = Al + 128 * LDA;
    __nv_bfloat16* Bl = Bh + 128 * LDA;
    int tid = threadIdx.x, lane = tid & 31, wid = tid >> 5;
    int rowBase = blockIdx.x * 128;

    stage_B(wimg, Bh, Bl, tid);
    stage_A(A, rowBase, M, Ah, Al, tid);
    __syncthreads();

    int warp_m = (wid & 3) * 32, warp_n = (wid >> 2) * 32;
    float acc[2][4][4];
#pragma unroll
    for (int mt = 0; mt < 2; mt++)
#pragma unroll
        for (int nt = 0; nt < 4; nt++)
#pragma unroll
            for (int q = 0; q < 4; q++) acc[mt][nt][q] = 0.f;

    int tq = lane >> 3, tr = lane & 7;
    int aoff = (warp_m + (tq & 1) * 8 + tr) * LDA + (tq >> 1) * 8;
    int boff = (warp_n + (tq >> 1) * 8 + tr) * LDA + (tq & 1) * 8;
    mma_3pass(Ah, Al, Bh, Bl, aoff, boff, acc);

#pragma unroll
    for (int mt = 0; mt < 2; mt++) {
#pragma unroll
        for (int half = 0; half < 2; half++) {
            int grow = rowBase + warp_m + mt * 16 + (lane >> 2) + half * 8;
            if (grow >= M) continue;
            float inv = 1.f;
            if (rowdiv) inv = 1.f / rowdiv[grow];
#pragma unroll
            for (int nt = 0; nt < 4; nt++) {
                int col = warp_n + nt * 8 + (lane & 3) * 2;
                float v0 = acc[mt][nt][half * 2 + 0];
                float v1 = acc[mt][nt][half * 2 + 1];
                if (rowdiv) { v0 *= inv; v1 *= inv; }
                if (colbias) { v0 += colbias[col]; v1 += colbias[col + 1]; }
                float* cp = &C[grow * H + col];
                if (RESID) {
                    float2 o = *(const float2*)cp;
                    v0 += o.x; v1 += o.y;
                }
                if (RELU) { v0 = fmaxf(v0, 0.f); v1 = fmaxf(v1, 0.f); }
                *(float2*)cp = make_float2(v0, v1);
            }
        }
    }
}

// ---------------- fused update GEMM ------------------------------------------
__global__ __launch_bounds__(512, 1) void gemm_u1(
    const float* __restrict__ A1, const float* __restrict__ A2,
    const unsigned char* __restrict__ w4, const unsigned char* __restrict__ w5,
    const float* __restrict__ gvec, const int* __restrict__ batch,
    float* __restrict__ T, int M) {
    extern __shared__ __align__(16) unsigned char smem[];
    __nv_bfloat16* Ah = (__nv_bfloat16*)smem;
    __nv_bfloat16* Al = Ah + 128 * LDA;
    __nv_bfloat16* Bh = Al + 128 * LDA;
    __nv_bfloat16* Bl = Bh + 128 * LDA;
    int tid = threadIdx.x, lane = tid & 31, wid = tid >> 5;
    int rowBase = blockIdx.x * 128;

    int warp_m = (wid & 3) * 32, warp_n = (wid >> 2) * 32;
    float acc[2][4][4];
#pragma unroll
    for (int mt = 0; mt < 2; mt++)
#pragma unroll
        for (int nt = 0; nt < 4; nt++)
#pragma unroll
            for (int q = 0; q < 4; q++) acc[mt][nt][q] = 0.f;

    int tq = lane >> 3, tr = lane & 7;
    int aoff = (warp_m + (tq & 1) * 8 + tr) * LDA + (tq >> 1) * 8;
    int boff = (warp_n + (tq >> 1) * 8 + tr) * LDA + (tq & 1) * 8;

    stage_B(w4, Bh, Bl, tid);
    stage_A(A1, rowBase, M, Ah, Al, tid);
    __syncthreads();
    mma_3pass(Ah, Al, Bh, Bl, aoff, boff, acc);
    __syncthreads();
    stage_B(w5, Bh, Bl, tid);
    stage_A(A2, rowBase, M, Ah, Al, tid);
    __syncthreads();
    mma_3pass(Ah, Al, Bh, Bl, aoff, boff, acc);

#pragma unroll
    for (int mt = 0; mt < 2; mt++) {
#pragma unroll
        for (int half = 0; half < 2; half++) {
            int grow = rowBase + warp_m + mt * 16 + (lane >> 2) + half * 8;
            if (grow >= M) continue;
            const float* gv = &gvec[batch[grow] * H];
#pragma unroll
            for (int nt = 0; nt < 4; nt++) {
                int col = warp_n + nt * 8 + (lane & 3) * 2;
                float v0 = acc[mt][nt][half * 2 + 0] + gv[col];
                float v1 = acc[mt][nt][half * 2 + 1] + gv[col + 1];
                *(float2*)&T[grow * H + col] =
                    make_float2(fmaxf(v0, 0.f), fmaxf(v1, 0.f));
            }
        }
    }
}

// ---------------- setup: zero, stats, CSR build ------------------------------
__global__ void zero_all_kernel() {
    int i = blockIdx.x * 256 + threadIdx.x;
    if (i < Nn) g_deg[i] = 0;
    if (i < REPEATS * Gg * H) ((float*)g_gsum3)[i] = 0.f;
    if (i < Gg * H) g_bcsum[i] = 0.f;
    if (i < Gg) { g_gc[i] = 0.f; g_bccnt[i] = 0.f; }
}

__global__ void node_stats_kernel(const int* __restrict__ batch,
                                  const float* __restrict__ x_mask) {
    __shared__ float sgc[Gg], sbc[Gg];
    int tid = threadIdx.x;
    if (tid < Gg) { sgc[tid] = 0.f; sbc[tid] = 0.f; }
    __syncthreads();
    int n = blockIdx.x * 256 + tid;
    if (n < Nn) {
        int g = batch[n];
        atomicAdd(&sgc[g], 1.f);
        atomicAdd(&sbc[g], x_mask[n * 3 + 2]);
    }
    __syncthreads();
    if (tid < Gg) {
        atomicAdd(&g_gc[tid], sgc[tid]);
        atomicAdd(&g_bccnt[tid], sbc[tid]);
    }
}

__global__ void hist_kernel(const int* __restrict__ ei) {
    int e = blockIdx.x * 256 + threadIdx.x;
    if (e < Ee) atomicAdd(&g_deg[ei[Ee + e]], 1);
}

// phase 1: per-block degree sums
__global__ void block_sum_kernel() {
    __shared__ int s[256];
    int tid = threadIdx.x;
    int n = blockIdx.x * 256 + tid;
    s[tid] = (n < Nn) ? g_deg[n] : 0;
    __syncthreads();
#pragma unroll
    for (int off = 128; off; off >>= 1) {
        if (tid < off) s[tid] += s[tid + off];
        __syncthreads();
    }
    if (tid == 0) g_bsum[blockIdx.x] = s[0];
}

// phase 2: exclusive scan of 196 block sums (single tiny block)
__global__ void scan_bsum_kernel() {
    __shared__ int s[256];
    int tid = threadIdx.x;
    int v = (tid < NB) ? g_bsum[tid] : 0;
    s[tid] = v;
    __syncthreads();
#pragma unroll
    for (int off = 1; off < 256; off <<= 1) {
        int t = (tid >= off) ? s[tid - off] : 0;
        __syncthreads();
        s[tid] += t;
        __syncthreads();
    }
    g_bsum[tid] = s[tid] - v;   // exclusive base per block
    if (tid == NB - 1) g_off[Nn] = s[tid];
}

// phase 3: intra-block scan + base -> offsets, cnt, fill
__global__ void write_off_kernel() {
    __shared__ int s[256];
    int tid = threadIdx.x;
    int n = blockIdx.x * 256 + tid;
    int v = (n < Nn) ? g_deg[n] : 0;
    s[tid] = v;
    __syncthreads();
#pragma unroll
    for (int off = 1; off < 256; off <<= 1) {
        int t = (tid >= off) ? s[tid - off] : 0;
        __syncthreads();
        s[tid] += t;
        __syncthreads();
    }
    if (n < Nn) {
        int base = g_bsum[blockIdx.x];
        g_off[n] = base + s[tid] - v;
        g_cnt[n] = (float)(v + 1);
        g_fill[n] = 0;
    }
}

__global__ void scatter_kernel(const int* __restrict__ ei) {
    int e = blockIdx.x * 256 + threadIdx.x;
    if (e >= Ee) return;
    int dst = ei[Ee + e];
    int pos = g_off[dst] + atomicAdd(&g_fill[dst], 1);
    g_esrc[pos] = ei[e];
    g_eidx[pos] = e;
}

// ---------------- encoder layer 1 --------------------------------------------
__global__ void enc1_kernel(const float* __restrict__ x,
                            const float* __restrict__ xm,
                            const float* __restrict__ W_e1,
                            const float* __restrict__ b_e1) {
    __shared__ float Ws[8 * H];
    __shared__ float bs[H];
    int tid = threadIdx.x;
    for (int i = tid; i < 8 * H; i += 256) Ws[i] = W_e1[i];
    if (tid < H) bs[tid] = b_e1[tid];
    __syncthreads();
    int idx = blockIdx.x * 256 + tid;
    if (idx >= Nn * 32) return;
    int n = idx >> 5, j4 = (idx & 31) * 4;
    float in8[8];
#pragma unroll
    for (int k = 0; k < 5; k++) in8[k] = x[n * 5 + k];
#pragma unroll
    for (int k = 0; k < 3; k++) in8[5 + k] = xm[n * 3 + k];
    float4 acc = *(const float4*)&bs[j4];
#pragma unroll
    for (int k = 0; k < 8; k++) {
        float4 w = *(const float4*)&Ws[k * H + j4];
        acc.x = fmaf(in8[k], w.x, acc.x);
        acc.y = fmaf(in8[k], w.y, acc.y);
        acc.z = fmaf(in8[k], w.z, acc.z);
        acc.w = fmaf(in8[k], w.w, acc.w);
    }
    acc.x = fmaxf(acc.x, 0.f); acc.y = fmaxf(acc.y, 0.f);
    acc.z = fmaxf(acc.z, 0.f); acc.w = fmaxf(acc.w, 0.f);
    *(float4*)&g_t[n * H + j4] = acc;
}

// ---------------- CSR edge kernel: one warp per dst node ---------------------
__global__ __launch_bounds__(256) void edge_csr_kernel(
    const float* __restrict__ ea, const float* __restrict__ W_m1) {
    __shared__ float Wea[3 * H];
    int tid = threadIdx.x;
    for (int i = tid; i < 3 * H; i += 256) Wea[i] = W_m1[256 * H + i];
    __syncthreads();
    int node = blockIdx.x * 8 + (tid >> 5);
    if (node >= Nn) return;
    int lane = tid & 31;
    int c = lane * 4;
    float4 qd = *(const float4*)&g_Q[node * H + c];
    float4 pd = *(const float4*)&g_P[node * H + c];
    float4 acc;
    acc.x = fmaxf(pd.x + qd.x, 0.f);
    acc.y = fmaxf(pd.y + qd.y, 0.f);
    acc.z = fmaxf(pd.z + qd.z, 0.f);
    acc.w = fmaxf(pd.w + qd.w, 0.f);
    float4 w0 = *(const float4*)&Wea[0 * H + c];
    float4 w1 = *(const float4*)&Wea[1 * H + c];
    float4 w2 = *(const float4*)&Wea[2 * H + c];
    int p0 = g_off[node], p1 = g_off[node + 1];
    for (int p = p0; p < p1; p++) {
        int src = g_esrc[p];
        int e = g_eidx[p];
        float e0 = __ldg(&ea[e * 3 + 0]);
        float e1 = __ldg(&ea[e * 3 + 1]);
        float e2 = __ldg(&ea[e * 3 + 2]);
        float4 ps = *(const float4*)&g_P[src * H + c];
        acc.x += fmaxf(ps.x + qd.x + e0 * w0.x + e1 * w1.x + e2 * w2.x, 0.f);
        acc.y += fmaxf(ps.y + qd.y + e0 * w0.y + e1 * w1.y + e2 * w2.y, 0.f);
        acc.z += fmaxf(ps.z + qd.z + e0 * w0.z + e1 * w1.z + e2 * w2.z, 0.f);
        acc.w += fmaxf(ps.w + qd.w + e0 * w0.w + e1 * w1.w + e2 * w2.w, 0.f);
    }
    *(float4*)&g_R[node * H + c] = acc;
}

// ---------------- group stats ------------------------------------------------
__global__ void group_sum_kernel(const int* __restrict__ batch,
                                 const float* __restrict__ x_mask,
                                 float* __restrict__ gsum, int withbc) {
    int j = threadIdx.x;
    int chunk = (Nn + gridDim.x - 1) / gridDim.x;
    int n0 = blockIdx.x * chunk;
    int n1 = n0 + chunk;
    if (n1 > Nn) n1 = Nn;
    if (n0 >= n1) return;
    float acc = 0.f, accb = 0.f;
    int gcur = batch[n0];
    for (int n = n0; n < n1; n++) {
        int g = batch[n];
        if (g != gcur) {
            atomicAdd(&gsum[gcur * H + j], acc);
            if (withbc) atomicAdd(&g_bcsum[gcur * H + j], accb);
            acc = 0.f; accb = 0.f; gcur = g;
        }
        float v = g_h[n * H + j];
        acc += v;
        if (withbc) accb += v * x_mask[n * 3 + 2];
    }
    atomicAdd(&gsum[gcur * H + j], acc);
    if (withbc) atomicAdd(&g_bcsum[gcur * H + j], accb);
}

__global__ void finalize_bc_kernel() {
    int g = blockIdx.x, j = threadIdx.x;
    float cb = fmaxf(g_bccnt[g], 1.f);
    g_xbc[g * H + j] = g_bcsum[g * H + j] / cb;
}

__global__ void fm_gvec_kernel(const float* __restrict__ gsum,
                               const float* __restrict__ W_u1,
                               const float* __restrict__ b_u1) {
    __shared__ float xg[H], xb[H];
    int g = blockIdx.x, j = threadIdx.x;
    float c = fmaxf(g_gc[g], 1.f);
    xg[j] = gsum[g * H + j] / c;
    xb[j] = g_xbc[g * H + j];
    __syncthreads();
    float acc = b_u1[j];
    for (int k = 0; k < H; k++) {
        acc = fmaf(xg[k], W_u1[(256 + k) * H + j], acc);
        acc = fmaf(xb[k], W_u1[(384 + k) * H + j], acc);
    }
    g_gvec[g * H + j] = acc;
}

__global__ void dec2_kernel(const float* __restrict__ W_d2,
                            const float* __restrict__ b_d2,
                            float* __restrict__ out) {
    int n = blockIdx.x * 8 + (threadIdx.x >> 5);
    if (n >= Nn) return;
    int lane = threadIdx.x & 31;
    float4 t4 = *(const float4*)&g_t[n * H + lane * 4];
    float tv[4] = {t4.x, t4.y, t4.z, t4.w};
    float a0 = 0.f, a1 = 0.f, a2 = 0.f;
#pragma unroll
    for (int r = 0; r < 4; r++) {
        int k = lane * 4 + r;
        a0 = fmaf(tv[r], __ldg(&W_d2[k * 3 + 0]), a0);
        a1 = fmaf(tv[r], __ldg(&W_d2[k * 3 + 1]), a1);
        a2 = fmaf(tv[r], __ldg(&W_d2[k * 3 + 2]), a2);
    }
#pragma unroll
    for (int off = 16; off; off >>= 1) {
        a0 += __shfl_down_sync(0xffffffffu, a0, off);
        a1 += __shfl_down_sync(0xffffffffu, a1, off);
        a2 += __shfl_down_sync(0xffffffffu, a2, off);
    }
    if (lane == 0) {
        out[n * 3 + 0] = a0 + b_d2[0];
        out[n * 3 + 1] = a1 + b_d2[1];
        out[n * 3 + 2] = a2 + b_d2[2];
    }
}

// ---------------- launch -----------------------------------------------------
extern "C" void kernel_launch(void* const* d_in, const int* in_sizes, int n_in,
                              void* d_out, int out_size) {
    const float* x    = (const float*)d_in[0];
    const float* xm   = (const float*)d_in[1];
    const float* ea   = (const float*)d_in[2];
    const float* W_e1 = (const float*)d_in[4];
    const float* b_e1 = (const float*)d_in[5];
    const float* W_e2 = (const float*)d_in[6];
    const float* b_e2 = (const float*)d_in[7];
    const float* W_m1 = (const float*)d_in[8];
    const float* b_m1 = (const float*)d_in[9];
    const float* W_m2 = (const float*)d_in[10];
    const float* b_m2 = (const float*)d_in[11];
    const float* W_u1 = (const float*)d_in[12];
    const float* b_u1 = (const float*)d_in[13];
    const float* W_u2 = (const float*)d_in[14];
    const float* b_u2 = (const float*)d_in[15];
    const float* W_d1 = (const float*)d_in[16];
    const float* b_d1 = (const float*)d_in[17];
    const float* W_d2 = (const float*)d_in[18];
    const float* b_d2 = (const float*)d_in[19];
    const int*   ei   = (const int*)d_in[20];
    const int*   batch = (const int*)d_in[21];
    float* out = (float*)d_out;

    float *p_h, *p_t, *p_P, *p_Q, *p_R, *p_agg, *p_cnt, *p_gvec, *p_gs;
    unsigned char* p_w;
    cudaGetSymbolAddress((void**)&p_h, g_h);
    cudaGetSymbolAddress((void**)&p_t, g_t);
    cudaGetSymbolAddress((void**)&p_P, g_P);
    cudaGetSymbolAddress((void**)&p_Q, g_Q);
    cudaGetSymbolAddress((void**)&p_R, g_R);
    cudaGetSymbolAddress((void**)&p_agg, g_agg);
    cudaGetSymbolAddress((void**)&p_cnt, g_cnt);
    cudaGetSymbolAddress((void**)&p_gvec, g_gvec);
    cudaGetSymbolAddress((void**)&p_gs, g_gsum3);
    cudaGetSymbolAddress((void**)&p_w, g_wimg);

    cudaFuncSetAttribute(gemm_tc<false, false>,
                         cudaFuncAttributeMaxDynamicSharedMemorySize, SMEM_G);
    cudaFuncSetAttribute(gemm_tc<true, false>,
                         cudaFuncAttributeMaxDynamicSharedMemorySize, SMEM_G);
    cudaFuncSetAttribute(gemm_tc<false, true>,
                         cudaFuncAttributeMaxDynamicSharedMemorySize, SMEM_G);
    cudaFuncSetAttribute(gemm_u1,
                         cudaFuncAttributeMaxDynamicSharedMemorySize, SMEM_G);

    const int GB = (Nn + 127) / 128;  // 391
#define IMG(i) (p_w + (i) * 65536)
#define GSUM(r) (p_gs + (r) * Gg * H)

    // setup + CSR build (parallel 3-phase scan)
    zero_all_kernel<<<NB, 256>>>();
    node_stats_kernel<<<NB, 256>>>(batch, xm);
    hist_kernel<<<(Ee + 255) / 256, 256>>>(ei);
    block_sum_kernel<<<NB, 256>>>();
    scan_bsum_kernel<<<1, 256>>>();
    write_off_kernel<<<NB, 256>>>();
    scatter_kernel<<<(Ee + 255) / 256, 256>>>(ei);
    wprep_kernel<<<512, 256>>>(W_e2, W_m1, W_m2, W_u1, W_u2, W_d1);

    // encoder
    enc1_kernel<<<(Nn * 32 + 255) / 256, 256>>>(x, xm, W_e1, b_e1);
    gemm_tc<false, false><<<GB, 512, SMEM_G>>>(p_t, IMG(0), b_e2, nullptr, p_h,
                                               Nn);

    group_sum_kernel<<<512, 128>>>(batch, xm, GSUM(0), 1);
    finalize_bc_kernel<<<Gg, 128>>>();

    for (int r = 0; r < REPEATS; r++) {
        fm_gvec_kernel<<<Gg, 128>>>(GSUM(r), W_u1, b_u1);
        gemm_tc<false, false><<<GB, 512, SMEM_G>>>(p_h, IMG(1), b_m1, nullptr,
                                                   p_P, Nn);
        gemm_tc<false, false><<<GB, 512, SMEM_G>>>(p_h, IMG(2), nullptr,
                                                   nullptr, p_Q, Nn);
        edge_csr_kernel<<<(Nn + 7) / 8, 256>>>(ea, W_m1);
        gemm_tc<false, false><<<GB, 512, SMEM_G>>>(p_R, IMG(3), b_m2, p_cnt,
                                                   p_agg, Nn);
        gemm_u1<<<GB, 512, SMEM_G>>>(p_h, p_agg, IMG(4), IMG(5), p_gvec, batch,
                                     p_t, Nn);
        gemm_tc<false, true><<<GB, 512, SMEM_G>>>(p_t, IMG(6), b_u2, nullptr,
                                                  p_h, Nn);
        if (r < REPEATS - 1)
            group_sum_kernel<<<512, 128>>>(batch, xm, GSUM(r + 1), 0);
    }

    // decoder
    gemm_tc<true, false><<<GB, 512, SMEM_G>>>(p_h, IMG(7), b_d1, nullptr, p_t,
                                              Nn);
    dec2_kernel<<<(Nn + 7) / 8, 256>>>(W_d2, b_d2, out);
}